// round 7
// baseline (speedup 1.0000x reference)
#include <cuda_runtime.h>
#include <cuda_bf16.h>
#include <cstdint>
#include <cstddef>

#define BATCH 4096
#define SEQ   60
#define INP   13
#define HID   128
#define GATES 512
#define MROWS (BATCH*SEQ)
#define BT    32
#define HPAD  34

#define BF_PER_LAYER (2*16*64*32)
#define BF_TOTAL     (2*BF_PER_LAYER)

// dynamic smem layout for rec kernel
#define WS_BYTES   65536                    // 2 x 16 x 512 floats
#define H2_BYTES   (128*HPAD*8)             // 34816
#define SMEM_REC   (WS_BYTES + H2_BYTES + 2048)

__device__ float g_xp[(size_t)2 * MROWS * GATES];
__device__ float g_y0[(size_t)MROWS * 256];
__device__ float g_y1[(size_t)MROWS * 256];
__device__ float g_whhP[6 * HID * GATES];   // packed per-thread layout
__device__ float g_w0P [2 * INP * GATES];
__device__ uint4 g_bfrag[BF_TOTAL];

typedef unsigned long long ull;

__device__ __forceinline__ ull pack_dup(float x) {
    ull r; asm("mov.b64 %0, {%1, %1};" : "=l"(r) : "f"(x)); return r;
}
__device__ __forceinline__ ull pack2(float x, float y) {
    ull r; asm("mov.b64 %0, {%1, %2};" : "=l"(r) : "f"(x), "f"(y)); return r;
}
__device__ __forceinline__ void unpack2(ull v, float& x, float& y) {
    asm("mov.b64 {%0, %1}, %2;" : "=f"(x), "=f"(y) : "l"(v));
}
__device__ __forceinline__ void fma2(ull& d, ull a, ull b) {
    asm("fma.rn.f32x2 %0, %1, %2, %3;" : "=l"(d) : "l"(a), "l"(b), "l"(d));
}
__device__ __forceinline__ float sigf(float x) { return __fdividef(1.f, 1.f + __expf(-x)); }
__device__ __forceinline__ float tanhf_(float x) {
    float ax = fabsf(x); float e = __expf(-2.f * ax);
    return copysignf(__fdividef(1.f - e, 1.f + e), x);
}
__device__ __forceinline__ uint32_t pack_bf2(float a, float b) {
    __nv_bfloat162 t = __floats2bfloat162_rn(a, b);
    return *reinterpret_cast<uint32_t*>(&t);
}
__device__ __forceinline__ void split_hl(float v, float& hi, float& lo) {
    __nv_bfloat16 h = __float2bfloat16_rn(v);
    hi = __bfloat162float(h);
    lo = v - hi;
}
__device__ __forceinline__ void mma16816(float c[4], const uint32_t a[4],
                                         uint32_t b0, uint32_t b1) {
    asm volatile("mma.sync.aligned.m16n8k16.row.col.f32.bf16.bf16.f32 "
                 "{%0,%1,%2,%3}, {%4,%5,%6,%7}, {%8,%9}, {%0,%1,%2,%3};"
                 : "+f"(c[0]), "+f"(c[1]), "+f"(c[2]), "+f"(c[3])
                 : "r"(a[0]), "r"(a[1]), "r"(a[2]), "r"(a[3]), "r"(b0), "r"(b1));
}
__device__ __forceinline__ void ldmx4(uint32_t r[4], const void* p) {
    uint32_t addr = (uint32_t)__cvta_generic_to_shared(p);
    asm volatile("ldmatrix.sync.aligned.m8n8.x4.shared.b16 {%0,%1,%2,%3}, [%4];"
                 : "=r"(r[0]), "=r"(r[1]), "=r"(r[2]), "=r"(r[3]) : "r"(addr));
}
__device__ __forceinline__ void cp_async16(uint32_t smem_dst, const void* gsrc) {
    asm volatile("cp.async.cg.shared.global [%0], [%1], 16;" :: "r"(smem_dst), "l"(gsrc));
}
__device__ __forceinline__ void cp_commit() { asm volatile("cp.async.commit_group;"); }
__device__ __forceinline__ void cp_wait0()  { asm volatile("cp.async.wait_group 0;"); }

struct WPtrs {
    const float* w_ih[6];
    const float* w_hh[6];
    const float* b_ih[6];
    const float* b_hh[6];
};

// packed layout: i = p*8 + g*2 + e  <->  gate element j = g*128 + p*2 + e
__global__ void prep_whhP(WPtrs P, float* __restrict__ dst) {
    int idx = blockIdx.x * 256 + threadIdx.x;
    if (idx >= 6 * HID * GATES) return;
    int w = idx / (HID * GATES), rem = idx % (HID * GATES);
    int k = rem / GATES, i = rem % GATES;
    int p = i >> 3, g = (i & 7) >> 1, e = i & 1;
    int j = g * 128 + p * 2 + e;
    dst[idx] = P.w_hh[w][j * HID + k];
}
__global__ void prep_w0P(WPtrs P, float* __restrict__ dst) {
    int idx = blockIdx.x * 256 + threadIdx.x;
    if (idx >= 2 * INP * GATES) return;
    int w = idx / (INP * GATES), rem = idx % (INP * GATES);
    int q = rem / GATES, i = rem % GATES;
    int p = i >> 3, g = (i & 7) >> 1, e = i & 1;
    int j = g * 128 + p * 2 + e;
    dst[idx] = P.w_ih[w][j * INP + q];
}
__global__ void prep_bfrag(WPtrs P, uint4* __restrict__ bf) {
    int idx = blockIdx.x * 256 + threadIdx.x;
    if (idx >= BF_TOTAL) return;
    int lane = idx & 31;
    int n8   = (idx >> 5) & 63;
    int kc   = (idx >> 11) & 15;
    int dir  = (idx >> 15) & 1;
    int layer = idx >> 16;
    const float* W = P.w_ih[2 + layer * 2 + dir];
    int n = n8 * 8 + (lane >> 2);
    int kb = kc * 16 + (lane & 3) * 2;
    float v00 = W[n * 256 + kb + 0], v01 = W[n * 256 + kb + 1];
    float v10 = W[n * 256 + kb + 8], v11 = W[n * 256 + kb + 9];
    float h00, l00, h01, l01, h10, l10, h11, l11;
    split_hl(v00, h00, l00); split_hl(v01, h01, l01);
    split_hl(v10, h10, l10); split_hl(v11, h11, l11);
    uint4 o;
    o.x = pack_bf2(h00, h01); o.y = pack_bf2(h10, h11);
    o.z = pack_bf2(l00, l01); o.w = pack_bf2(l10, l11);
    bf[idx] = o;
}
__global__ void dummy_kernel() {}

// ---- split-bf16 tensor-core projection GEMM; epilogue writes PACKED xp ----
__global__ __launch_bounds__(256, 1)
void gemm_mma(const float* __restrict__ A,
              const uint4* __restrict__ bfrag,
              const float* __restrict__ bihF, const float* __restrict__ bhhF,
              const float* __restrict__ bihB, const float* __restrict__ bhhB,
              float* __restrict__ xp)
{
    const int dir = blockIdx.z;
    const int m0  = blockIdx.x * 128;
    const int n0  = blockIdx.y * 128;
    const int tid = threadIdx.x;
    const int lane = tid & 31, wid = tid >> 5;
    const int wm = wid & 3, wn = wid >> 2;
    const float* bih = dir ? bihB : bihF;
    const float* bhh = dir ? bhhB : bhhF;

    __shared__ __align__(16) uint16_t Asm[2][128][24];

    float acc[2][8][4];
#pragma unroll
    for (int a = 0; a < 2; a++)
#pragma unroll
        for (int b = 0; b < 8; b++)
#pragma unroll
            for (int c = 0; c < 4; c++) acc[a][b][c] = 0.f;

    const int lrow0 = wm * 32 + (lane & 7) + ((lane >> 3) & 1) * 8;
    const int lkb   = (lane & 16) ? 8 : 0;
    const int arow = tid & 127;
    const int ach  = tid >> 7;

    for (int kc = 0; kc < 16; ++kc) {
        {
            const float4* src = reinterpret_cast<const float4*>(
                &A[(size_t)(m0 + arow) * 256 + kc * 16 + ach * 8]);
            float4 v0 = src[0], v1 = src[1];
            float hv[8], lv[8];
            split_hl(v0.x, hv[0], lv[0]); split_hl(v0.y, hv[1], lv[1]);
            split_hl(v0.z, hv[2], lv[2]); split_hl(v0.w, hv[3], lv[3]);
            split_hl(v1.x, hv[4], lv[4]); split_hl(v1.y, hv[5], lv[5]);
            split_hl(v1.z, hv[6], lv[6]); split_hl(v1.w, hv[7], lv[7]);
            uint4 ph, pl;
            ph.x = pack_bf2(hv[0], hv[1]); ph.y = pack_bf2(hv[2], hv[3]);
            ph.z = pack_bf2(hv[4], hv[5]); ph.w = pack_bf2(hv[6], hv[7]);
            pl.x = pack_bf2(lv[0], lv[1]); pl.y = pack_bf2(lv[2], lv[3]);
            pl.z = pack_bf2(lv[4], lv[5]); pl.w = pack_bf2(lv[6], lv[7]);
            *reinterpret_cast<uint4*>(&Asm[0][arow][ach * 8]) = ph;
            *reinterpret_cast<uint4*>(&Asm[1][arow][ach * 8]) = pl;
        }
        __syncthreads();

        uint4 bf[8];
        const int nbase = blockIdx.y * 16 + wn * 8;
#pragma unroll
        for (int i = 0; i < 8; ++i)
            bf[i] = bfrag[(((size_t)(dir * 16 + kc) * 64) + nbase + i) * 32 + lane];

        uint32_t ah[2][4], al[2][4];
#pragma unroll
        for (int ms = 0; ms < 2; ++ms) {
            ldmx4(ah[ms], &Asm[0][lrow0 + ms * 16][lkb]);
            ldmx4(al[ms], &Asm[1][lrow0 + ms * 16][lkb]);
        }

#pragma unroll
        for (int i = 0; i < 8; ++i) {
#pragma unroll
            for (int ms = 0; ms < 2; ++ms) {
                mma16816(acc[ms][i], ah[ms], bf[i].x, bf[i].y);
                mma16816(acc[ms][i], ah[ms], bf[i].z, bf[i].w);
                mma16816(acc[ms][i], al[ms], bf[i].x, bf[i].y);
            }
        }
        __syncthreads();
    }

    const int g  = lane >> 2;
    const int t2 = (lane & 3) * 2;
#pragma unroll
    for (int ms = 0; ms < 2; ++ms) {
#pragma unroll
        for (int i = 0; i < 8; ++i) {
            int j = n0 + wn * 64 + i * 8 + t2;          // natural gate col (even)
            float b0 = bih[j] + bhh[j];
            float b1 = bih[j + 1] + bhh[j + 1];
            int gg = j >> 7, cc = j & 127;
            int pw = (cc >> 1) * 8 + gg * 2;            // packed position
            size_t r0 = (size_t)dir * MROWS + m0 + wm * 32 + ms * 16 + g;
            *reinterpret_cast<float2*>(&xp[r0 * 512 + pw]) =
                make_float2(acc[ms][i][0] + b0, acc[ms][i][1] + b1);
            *reinterpret_cast<float2*>(&xp[(r0 + 8) * 512 + pw]) =
                make_float2(acc[ms][i][2] + b0, acc[ms][i][3] + b1);
        }
    }
}

// ---- recurrence kernel: cp.async smem-staged weights, fma-bound target ----
__global__ __launch_bounds__(256, 2)
void lstm_rec_kernel(const float* __restrict__ xp, const float* __restrict__ x,
                     const float* __restrict__ w0P,
                     const float* __restrict__ bihF, const float* __restrict__ bhhF,
                     const float* __restrict__ bihB, const float* __restrict__ bhhB,
                     const float* __restrict__ whhPF, const float* __restrict__ whhPB,
                     float* __restrict__ y, int is_layer0)
{
    extern __shared__ __align__(16) char sm[];
    float* ws = reinterpret_cast<float*>(sm);                       // [2][16][512]
    ull*   h2 = reinterpret_cast<ull*>(sm + WS_BYTES);              // [128][HPAD]
    float (*xsm)[16] = reinterpret_cast<float(*)[16]>(sm + WS_BYTES + H2_BYTES);

    const int dir = blockIdx.y;
    const int b0  = blockIdx.x * BT;
    const int tid = threadIdx.x;
    const int bg  = tid >> 6;
    const int p   = tid & 63;
    const int hc0 = p * 2;
    const float* wdir = dir ? whhPB : whhPF;

    const uint32_t ws_u32 = (uint32_t)__cvta_generic_to_shared(ws);

    for (int i = tid; i < 128 * HPAD; i += 256) h2[i] = 0ull;

    ull c2[8];
#pragma unroll
    for (int i = 0; i < 8; i++) c2[i] = 0ull;

    ull bias2[4];
    const float* w0 = w0P + (size_t)dir * INP * GATES;
    if (is_layer0) {
        const float* bi = dir ? bihB : bihF;
        const float* bh = dir ? bhhB : bhhF;
#pragma unroll
        for (int g = 0; g < 4; g++) {
            int j = g * 128 + hc0;
            bias2[g] = pack2(bi[j] + bh[j], bi[j + 1] + bh[j + 1]);
        }
        int t0 = dir ? (SEQ - 1) : 0;
        for (int i = tid; i < BT * INP; i += 256) {
            int b = i / INP, q = i % INP;
            xsm[b][q] = x[((size_t)(b0 + b) * SEQ + t0) * INP + q];
        }
    }
    __syncthreads();

    // prologue: prefetch chunk 0 into buffer 0
#pragma unroll
    for (int j = 0; j < 8; ++j)
        cp_async16(ws_u32 + (j * 256 + tid) * 16, wdir + (j * 256 + tid) * 4);
    cp_commit();

    const size_t xpdir = (size_t)dir * MROWS * GATES;
    int buf = 0;

    for (int s = 0; s < SEQ; ++s) {
        const int t = dir ? (SEQ - 1 - s) : s;
        ull acc[8][4];

        if (is_layer0) {
#pragma unroll
            for (int bb = 0; bb < 8; ++bb)
#pragma unroll
                for (int g = 0; g < 4; ++g) acc[bb][g] = bias2[g];
#pragma unroll
            for (int q = 0; q < INP; ++q) {
                const ulonglong2* wq =
                    reinterpret_cast<const ulonglong2*>(w0 + (size_t)q * GATES + p * 8);
                ulonglong2 u0 = wq[0], u1 = wq[1];
#pragma unroll
                for (int bb = 0; bb < 8; ++bb) {
                    ull xd = pack_dup(xsm[bg * 8 + bb][q]);
                    fma2(acc[bb][0], xd, u0.x); fma2(acc[bb][1], xd, u0.y);
                    fma2(acc[bb][2], xd, u1.x); fma2(acc[bb][3], xd, u1.y);
                }
            }
        } else {
#pragma unroll
            for (int bb = 0; bb < 8; ++bb) {
                const ulonglong2* xpp = reinterpret_cast<const ulonglong2*>(
                    xp + xpdir + ((size_t)(b0 + bg * 8 + bb) * SEQ + t) * GATES + p * 8);
                ulonglong2 a0 = xpp[0], a1 = xpp[1];
                acc[bb][0] = a0.x; acc[bb][1] = a0.y;
                acc[bb][2] = a1.x; acc[bb][3] = a1.y;
            }
        }

        // 8 chunks of 16 k-rows, double-buffered through smem
        for (int c = 0; c < 8; ++c) {
            cp_wait0();
            __syncthreads();      // chunk c visible to all; all done reading buf^1
            // prefetch next chunk (wraps to 0 for next step)
            {
                int nc = (c + 1) & 7;
                const float* src = wdir + (size_t)nc * 8192;
                uint32_t dst = ws_u32 + (buf ^ 1) * 32768;
#pragma unroll
                for (int j = 0; j < 8; ++j)
                    cp_async16(dst + (j * 256 + tid) * 16, src + (j * 256 + tid) * 4);
                cp_commit();
            }
            const float* wsb = ws + buf * 8192;
#pragma unroll
            for (int kk = 0; kk < 16; ++kk) {
                const ulonglong2* wr =
                    reinterpret_cast<const ulonglong2*>(wsb + kk * 512 + p * 8);
                ulonglong2 u0 = wr[0], u1 = wr[1];
                const ulonglong2* hrow = reinterpret_cast<const ulonglong2*>(
                    &h2[(size_t)(c * 16 + kk) * HPAD + bg * 8]);
                ulonglong2 hv01 = hrow[0], hv23 = hrow[1], hv45 = hrow[2], hv67 = hrow[3];
                fma2(acc[0][0], hv01.x, u0.x); fma2(acc[0][1], hv01.x, u0.y);
                fma2(acc[0][2], hv01.x, u1.x); fma2(acc[0][3], hv01.x, u1.y);
                fma2(acc[1][0], hv01.y, u0.x); fma2(acc[1][1], hv01.y, u0.y);
                fma2(acc[1][2], hv01.y, u1.x); fma2(acc[1][3], hv01.y, u1.y);
                fma2(acc[2][0], hv23.x, u0.x); fma2(acc[2][1], hv23.x, u0.y);
                fma2(acc[2][2], hv23.x, u1.x); fma2(acc[2][3], hv23.x, u1.y);
                fma2(acc[3][0], hv23.y, u0.x); fma2(acc[3][1], hv23.y, u0.y);
                fma2(acc[3][2], hv23.y, u1.x); fma2(acc[3][3], hv23.y, u1.y);
                fma2(acc[4][0], hv45.x, u0.x); fma2(acc[4][1], hv45.x, u0.y);
                fma2(acc[4][2], hv45.x, u1.x); fma2(acc[4][3], hv45.x, u1.y);
                fma2(acc[5][0], hv45.y, u0.x); fma2(acc[5][1], hv45.y, u0.y);
                fma2(acc[5][2], hv45.y, u1.x); fma2(acc[5][3], hv45.y, u1.y);
                fma2(acc[6][0], hv67.x, u0.x); fma2(acc[6][1], hv67.x, u0.y);
                fma2(acc[6][2], hv67.x, u1.x); fma2(acc[6][3], hv67.x, u1.y);
                fma2(acc[7][0], hv67.y, u0.x); fma2(acc[7][1], hv67.y, u0.y);
                fma2(acc[7][2], hv67.y, u1.x); fma2(acc[7][3], hv67.y, u1.y);
            }
            buf ^= 1;
        }
        __syncthreads();   // all reads of h2 done

#pragma unroll
        for (int bb = 0; bb < 8; ++bb) {
            float i0, i1, f0, f1, g0, g1, o0, o1, cc0, cc1;
            unpack2(acc[bb][0], i0, i1); unpack2(acc[bb][1], f0, f1);
            unpack2(acc[bb][2], g0, g1); unpack2(acc[bb][3], o0, o1);
            unpack2(c2[bb], cc0, cc1);
            cc0 = sigf(f0) * cc0 + sigf(i0) * tanhf_(g0);
            cc1 = sigf(f1) * cc1 + sigf(i1) * tanhf_(g1);
            float h0 = sigf(o0) * tanhf_(cc0);
            float h1 = sigf(o1) * tanhf_(cc1);
            c2[bb] = pack2(cc0, cc1);
            int b = bg * 8 + bb;
            h2[(hc0)     * HPAD + b] = pack_dup(h0);
            h2[(hc0 + 1) * HPAD + b] = pack_dup(h1);
            *reinterpret_cast<float2*>(
                &y[((size_t)(b0 + b) * SEQ + t) * 256 + dir * 128 + hc0]) = make_float2(h0, h1);
        }
        if (is_layer0 && s < SEQ - 1) {
            int tn = dir ? (SEQ - 2 - s) : (s + 1);
            for (int i = tid; i < BT * INP; i += 256) {
                int b = i / INP, q = i % INP;
                xsm[b][q] = x[((size_t)(b0 + b) * SEQ + tn) * INP + q];
            }
        }
        __syncthreads();   // h2 / xsm ready for next step
    }
}

__global__ void final_kernel(const float* __restrict__ y, const float* __restrict__ wout,
                             const float* __restrict__ bout, float* __restrict__ out)
{
    const int b = blockIdx.x;
    const int tid = threadIdx.x;
    const float* yr = y + (size_t)b * 15360;
    float s0 = 0.f, s1 = 0.f;
    for (int j = tid * 4; j < 15360; j += 128 * 4) {
        float4 v = *reinterpret_cast<const float4*>(&yr[j]);
        v.x = fmaxf(v.x, 0.f); v.y = fmaxf(v.y, 0.f);
        v.z = fmaxf(v.z, 0.f); v.w = fmaxf(v.w, 0.f);
        float4 w0 = __ldg(reinterpret_cast<const float4*>(&wout[j]));
        float4 w1 = __ldg(reinterpret_cast<const float4*>(&wout[15360 + j]));
        s0 += v.x * w0.x + v.y * w0.y + v.z * w0.z + v.w * w0.w;
        s1 += v.x * w1.x + v.y * w1.y + v.z * w1.z + v.w * w1.w;
    }
#pragma unroll
    for (int off = 16; off > 0; off >>= 1) {
        s0 += __shfl_down_sync(0xffffffffu, s0, off);
        s1 += __shfl_down_sync(0xffffffffu, s1, off);
    }
    __shared__ float r0[4], r1[4];
    int wid = tid >> 5;
    if ((tid & 31) == 0) { r0[wid] = s0; r1[wid] = s1; }
    __syncthreads();
    if (tid == 0) {
        out[(size_t)b * 2 + 0] = r0[0] + r0[1] + r0[2] + r0[3] + __ldg(&bout[0]);
        out[(size_t)b * 2 + 1] = r1[0] + r1[1] + r1[2] + r1[3] + __ldg(&bout[1]);
    }
}

extern "C" void kernel_launch(void* const* d_in, const int* in_sizes, int n_in,
                              void* d_out, int out_size) {
    const float* x = (const float*)d_in[0];
    WPtrs P;
    for (int i = 0; i < 6; i++) {
        P.w_ih[i] = (const float*)d_in[1 + 4 * i];
        P.w_hh[i] = (const float*)d_in[2 + 4 * i];
        P.b_ih[i] = (const float*)d_in[3 + 4 * i];
        P.b_hh[i] = (const float*)d_in[4 + 4 * i];
    }
    const float* w_out = (const float*)d_in[25];
    const float* b_out = (const float*)d_in[26];
    float* out = (float*)d_out;

    float *xp, *y0, *y1, *whhP, *w0P; uint4* bfrag;
    cudaGetSymbolAddress((void**)&xp,    g_xp);
    cudaGetSymbolAddress((void**)&y0,    g_y0);
    cudaGetSymbolAddress((void**)&y1,    g_y1);
    cudaGetSymbolAddress((void**)&whhP,  g_whhP);
    cudaGetSymbolAddress((void**)&w0P,   g_w0P);
    cudaGetSymbolAddress((void**)&bfrag, g_bfrag);

    cudaFuncSetAttribute(lstm_rec_kernel,
                         cudaFuncAttributeMaxDynamicSharedMemorySize, SMEM_REC);

    prep_whhP<<<(6 * HID * GATES + 255) / 256, 256>>>(P, whhP);       // 0
    prep_w0P<<<(2 * INP * GATES + 255) / 256, 256>>>(P, w0P);         // 1
    prep_bfrag<<<(BF_TOTAL + 255) / 256, 256>>>(P, bfrag);            // 2

    dim3 rgrid(BATCH / BT, 2);
    dim3 ggrid(MROWS / 128, GATES / 128, 2);

    lstm_rec_kernel<<<rgrid, 256, SMEM_REC>>>(nullptr, x, w0P,        // 3
                                    P.b_ih[0], P.b_hh[0], P.b_ih[1], P.b_hh[1],
                                    whhP + 0 * (size_t)HID * GATES, whhP + 1 * (size_t)HID * GATES,
                                    y0, 1);
    dummy_kernel<<<1, 32>>>();                                        // 4
    gemm_mma<<<ggrid, 256>>>(y0, bfrag,                               // 5  (ncu -s 5)
                             P.b_ih[2], P.b_hh[2], P.b_ih[3], P.b_hh[3], xp);
    lstm_rec_kernel<<<rgrid, 256, SMEM_REC>>>(xp, nullptr, nullptr,   // 6
                                    P.b_ih[2], P.b_hh[2], P.b_ih[3], P.b_hh[3],
                                    whhP + 2 * (size_t)HID * GATES, whhP + 3 * (size_t)HID * GATES,
                                    y1, 0);
    gemm_mma<<<ggrid, 256>>>(y1, bfrag + BF_PER_LAYER,                // 7
                             P.b_ih[4], P.b_hh[4], P.b_ih[5], P.b_hh[5], xp);
    lstm_rec_kernel<<<rgrid, 256, SMEM_REC>>>(xp, nullptr, nullptr,   // 8
                                    P.b_ih[4], P.b_hh[4], P.b_ih[5], P.b_hh[5],
                                    whhP + 4 * (size_t)HID * GATES, whhP + 5 * (size_t)HID * GATES,
                                    y0, 0);
    final_kernel<<<BATCH, 128>>>(y0, w_out, b_out, out);              // 9
}

// round 8
// speedup vs baseline: 1.0132x; 1.0132x over previous
#include <cuda_runtime.h>
#include <cuda_bf16.h>
#include <cstdint>
#include <cstddef>

#define BATCH 4096
#define SEQ   60
#define INP   13
#define HID   128
#define GATES 512
#define MROWS (BATCH*SEQ)
#define BT    64
#define BPAD  68

#define BF_PER_LAYER (2*16*64*32)
#define BF_TOTAL     (2*BF_PER_LAYER)

__device__ float g_xp[(size_t)2 * MROWS * GATES];
__device__ float g_y0[(size_t)MROWS * 256];
__device__ float g_y1[(size_t)MROWS * 256];
__device__ float g_whhP[6 * HID * GATES];   // packed per-thread layout
__device__ float g_w0P [2 * INP * GATES];
__device__ uint4 g_bfrag[BF_TOTAL];

typedef unsigned long long ull;

__device__ __forceinline__ ull pack_dup(float x) {
    ull r; asm("mov.b64 %0, {%1, %1};" : "=l"(r) : "f"(x)); return r;
}
__device__ __forceinline__ ull pack2(float x, float y) {
    ull r; asm("mov.b64 %0, {%1, %2};" : "=l"(r) : "f"(x), "f"(y)); return r;
}
__device__ __forceinline__ void unpack2(ull v, float& x, float& y) {
    asm("mov.b64 {%0, %1}, %2;" : "=f"(x), "=f"(y) : "l"(v));
}
__device__ __forceinline__ void fma2(ull& d, ull a, ull b) {
    asm("fma.rn.f32x2 %0, %1, %2, %3;" : "=l"(d) : "l"(a), "l"(b), "l"(d));
}
__device__ __forceinline__ float sigf(float x) { return __fdividef(1.f, 1.f + __expf(-x)); }
__device__ __forceinline__ float tanhf_(float x) {
    float ax = fabsf(x); float e = __expf(-2.f * ax);
    return copysignf(__fdividef(1.f - e, 1.f + e), x);
}
__device__ __forceinline__ uint32_t pack_bf2(float a, float b) {
    __nv_bfloat162 t = __floats2bfloat162_rn(a, b);
    return *reinterpret_cast<uint32_t*>(&t);
}
__device__ __forceinline__ void split_hl(float v, float& hi, float& lo) {
    __nv_bfloat16 h = __float2bfloat16_rn(v);
    hi = __bfloat162float(h);
    lo = v - hi;
}
__device__ __forceinline__ void mma16816(float c[4], const uint32_t a[4],
                                         uint32_t b0, uint32_t b1) {
    asm volatile("mma.sync.aligned.m16n8k16.row.col.f32.bf16.bf16.f32 "
                 "{%0,%1,%2,%3}, {%4,%5,%6,%7}, {%8,%9}, {%0,%1,%2,%3};"
                 : "+f"(c[0]), "+f"(c[1]), "+f"(c[2]), "+f"(c[3])
                 : "r"(a[0]), "r"(a[1]), "r"(a[2]), "r"(a[3]), "r"(b0), "r"(b1));
}
__device__ __forceinline__ void ldmx4(uint32_t r[4], const void* p) {
    uint32_t addr = (uint32_t)__cvta_generic_to_shared(p);
    asm volatile("ldmatrix.sync.aligned.m8n8.x4.shared.b16 {%0,%1,%2,%3}, [%4];"
                 : "=r"(r[0]), "=r"(r[1]), "=r"(r[2]), "=r"(r[3]) : "r"(addr));
}

struct WPtrs {
    const float* w_ih[6];
    const float* w_hh[6];
    const float* b_ih[6];
    const float* b_hh[6];
};

// packed layout: i = p*8 + g*2 + e  <->  gate element j = g*128 + p*2 + e
__global__ void prep_whhP(WPtrs P, float* __restrict__ dst) {
    int idx = blockIdx.x * 256 + threadIdx.x;
    if (idx >= 6 * HID * GATES) return;
    int w = idx / (HID * GATES), rem = idx % (HID * GATES);
    int k = rem / GATES, i = rem % GATES;
    int p = i >> 3, g = (i & 7) >> 1, e = i & 1;
    int j = g * 128 + p * 2 + e;
    dst[idx] = P.w_hh[w][j * HID + k];
}
__global__ void prep_w0P(WPtrs P, float* __restrict__ dst) {
    int idx = blockIdx.x * 256 + threadIdx.x;
    if (idx >= 2 * INP * GATES) return;
    int w = idx / (INP * GATES), rem = idx % (INP * GATES);
    int q = rem / GATES, i = rem % GATES;
    int p = i >> 3, g = (i & 7) >> 1, e = i & 1;
    int j = g * 128 + p * 2 + e;
    dst[idx] = P.w_ih[w][j * INP + q];
}
__global__ void prep_bfrag(WPtrs P, uint4* __restrict__ bf) {
    int idx = blockIdx.x * 256 + threadIdx.x;
    if (idx >= BF_TOTAL) return;
    int lane = idx & 31;
    int n8   = (idx >> 5) & 63;
    int kc   = (idx >> 11) & 15;
    int dir  = (idx >> 15) & 1;
    int layer = idx >> 16;
    const float* W = P.w_ih[2 + layer * 2 + dir];
    int n = n8 * 8 + (lane >> 2);
    int kb = kc * 16 + (lane & 3) * 2;
    float v00 = W[n * 256 + kb + 0], v01 = W[n * 256 + kb + 1];
    float v10 = W[n * 256 + kb + 8], v11 = W[n * 256 + kb + 9];
    float h00, l00, h01, l01, h10, l10, h11, l11;
    split_hl(v00, h00, l00); split_hl(v01, h01, l01);
    split_hl(v10, h10, l10); split_hl(v11, h11, l11);
    uint4 o;
    o.x = pack_bf2(h00, h01); o.y = pack_bf2(h10, h11);
    o.z = pack_bf2(l00, l01); o.w = pack_bf2(l10, l11);
    bf[idx] = o;
}

// ---- split-bf16 tensor-core projection GEMM; epilogue writes PACKED xp ----
__global__ __launch_bounds__(256, 1)
void gemm_mma(const float* __restrict__ A,
              const uint4* __restrict__ bfrag,
              const float* __restrict__ bihF, const float* __restrict__ bhhF,
              const float* __restrict__ bihB, const float* __restrict__ bhhB,
              float* __restrict__ xp)
{
    const int dir = blockIdx.z;
    const int m0  = blockIdx.x * 128;
    const int n0  = blockIdx.y * 128;
    const int tid = threadIdx.x;
    const int lane = tid & 31, wid = tid >> 5;
    const int wm = wid & 3, wn = wid >> 2;
    const float* bih = dir ? bihB : bihF;
    const float* bhh = dir ? bhhB : bhhF;

    __shared__ __align__(16) uint16_t Asm[2][128][24];

    float acc[2][8][4];
#pragma unroll
    for (int a = 0; a < 2; a++)
#pragma unroll
        for (int b = 0; b < 8; b++)
#pragma unroll
            for (int c = 0; c < 4; c++) acc[a][b][c] = 0.f;

    const int lrow0 = wm * 32 + (lane & 7) + ((lane >> 3) & 1) * 8;
    const int lkb   = (lane & 16) ? 8 : 0;
    const int arow = tid & 127;
    const int ach  = tid >> 7;

    for (int kc = 0; kc < 16; ++kc) {
        {
            const float4* src = reinterpret_cast<const float4*>(
                &A[(size_t)(m0 + arow) * 256 + kc * 16 + ach * 8]);
            float4 v0 = src[0], v1 = src[1];
            float hv[8], lv[8];
            split_hl(v0.x, hv[0], lv[0]); split_hl(v0.y, hv[1], lv[1]);
            split_hl(v0.z, hv[2], lv[2]); split_hl(v0.w, hv[3], lv[3]);
            split_hl(v1.x, hv[4], lv[4]); split_hl(v1.y, hv[5], lv[5]);
            split_hl(v1.z, hv[6], lv[6]); split_hl(v1.w, hv[7], lv[7]);
            uint4 ph, pl;
            ph.x = pack_bf2(hv[0], hv[1]); ph.y = pack_bf2(hv[2], hv[3]);
            ph.z = pack_bf2(hv[4], hv[5]); ph.w = pack_bf2(hv[6], hv[7]);
            pl.x = pack_bf2(lv[0], lv[1]); pl.y = pack_bf2(lv[2], lv[3]);
            pl.z = pack_bf2(lv[4], lv[5]); pl.w = pack_bf2(lv[6], lv[7]);
            *reinterpret_cast<uint4*>(&Asm[0][arow][ach * 8]) = ph;
            *reinterpret_cast<uint4*>(&Asm[1][arow][ach * 8]) = pl;
        }
        __syncthreads();

        uint4 bf[8];
        const int nbase = blockIdx.y * 16 + wn * 8;
#pragma unroll
        for (int i = 0; i < 8; ++i)
            bf[i] = bfrag[(((size_t)(dir * 16 + kc) * 64) + nbase + i) * 32 + lane];

        uint32_t ah[2][4], al[2][4];
#pragma unroll
        for (int ms = 0; ms < 2; ++ms) {
            ldmx4(ah[ms], &Asm[0][lrow0 + ms * 16][lkb]);
            ldmx4(al[ms], &Asm[1][lrow0 + ms * 16][lkb]);
        }

#pragma unroll
        for (int i = 0; i < 8; ++i) {
#pragma unroll
            for (int ms = 0; ms < 2; ++ms) {
                mma16816(acc[ms][i], ah[ms], bf[i].x, bf[i].y);
                mma16816(acc[ms][i], ah[ms], bf[i].z, bf[i].w);
                mma16816(acc[ms][i], al[ms], bf[i].x, bf[i].y);
            }
        }
        __syncthreads();
    }

    const int g  = lane >> 2;
    const int t2 = (lane & 3) * 2;
#pragma unroll
    for (int ms = 0; ms < 2; ++ms) {
#pragma unroll
        for (int i = 0; i < 8; ++i) {
            int j = n0 + wn * 64 + i * 8 + t2;          // natural gate col (even)
            float b0 = bih[j] + bhh[j];
            float b1 = bih[j + 1] + bhh[j + 1];
            int gg = j >> 7, cc = j & 127;
            int pw = (cc >> 1) * 8 + gg * 2;            // packed position
            size_t r0 = (size_t)dir * MROWS + m0 + wm * 32 + ms * 16 + g;
            *reinterpret_cast<float2*>(&xp[r0 * 512 + pw]) =
                make_float2(acc[ms][i][0] + b0, acc[ms][i][1] + b1);
            *reinterpret_cast<float2*>(&xp[(r0 + 8) * 512 + pw]) =
                make_float2(acc[ms][i][2] + b0, acc[ms][i][3] + b1);
        }
    }
}

// ---- recurrence: BT=64, 16 rows/thread, broadcast h, LDG.128 weights ----
__global__ __launch_bounds__(256, 1)
void lstm_rec_kernel(const float* __restrict__ xp, const float* __restrict__ x,
                     const float* __restrict__ w0P,
                     const float* __restrict__ bihF, const float* __restrict__ bhhF,
                     const float* __restrict__ bihB, const float* __restrict__ bhhB,
                     const float* __restrict__ whhPF, const float* __restrict__ whhPB,
                     float* __restrict__ y, int is_layer0)
{
    const int dir = blockIdx.y;
    const int b0  = blockIdx.x * BT;
    const int tid = threadIdx.x;
    const int bg  = tid >> 6;          // 0..3, 16 batch rows each
    const int p   = tid & 63;
    const int hc0 = p * 2;
    const float* wdir = dir ? whhPB : whhPF;

    __shared__ float hs[128 * BPAD];        // plain h, row-major [k][b]
    __shared__ float xsm[BT][16];

    for (int i = tid; i < 128 * BPAD; i += 256) hs[i] = 0.f;

    ull c2[16];
#pragma unroll
    for (int i = 0; i < 16; i++) c2[i] = 0ull;

    ull bias2[4];
    const float* w0 = w0P + (size_t)dir * INP * GATES;
    if (is_layer0) {
        const float* bi = dir ? bihB : bihF;
        const float* bh = dir ? bhhB : bhhF;
#pragma unroll
        for (int g = 0; g < 4; g++) {
            int j = g * 128 + hc0;
            bias2[g] = pack2(bi[j] + bh[j], bi[j + 1] + bh[j + 1]);
        }
        int t0 = dir ? (SEQ - 1) : 0;
        for (int i = tid; i < BT * INP; i += 256) {
            int b = i / INP, q = i % INP;
            xsm[b][q] = x[((size_t)(b0 + b) * SEQ + t0) * INP + q];
        }
    }
    __syncthreads();

    const size_t xpdir = (size_t)dir * MROWS * GATES;

    for (int s = 0; s < SEQ; ++s) {
        const int t = dir ? (SEQ - 1 - s) : s;
        ull acc[16][4];

        if (is_layer0) {
#pragma unroll
            for (int bb = 0; bb < 16; ++bb)
#pragma unroll
                for (int g = 0; g < 4; ++g) acc[bb][g] = bias2[g];
#pragma unroll
            for (int q = 0; q < INP; ++q) {
                const ulonglong2* wq =
                    reinterpret_cast<const ulonglong2*>(w0 + (size_t)q * GATES + p * 8);
                ulonglong2 u0 = wq[0], u1 = wq[1];
#pragma unroll
                for (int bb = 0; bb < 16; ++bb) {
                    ull xd = pack_dup(xsm[bg * 16 + bb][q]);
                    fma2(acc[bb][0], xd, u0.x); fma2(acc[bb][1], xd, u0.y);
                    fma2(acc[bb][2], xd, u1.x); fma2(acc[bb][3], xd, u1.y);
                }
            }
        } else {
#pragma unroll
            for (int bb = 0; bb < 16; ++bb) {
                const ulonglong2* xpp = reinterpret_cast<const ulonglong2*>(
                    xp + xpdir + ((size_t)(b0 + bg * 16 + bb) * SEQ + t) * GATES + p * 8);
                ulonglong2 a0 = xpp[0], a1 = xpp[1];
                acc[bb][0] = a0.x; acc[bb][1] = a0.y;
                acc[bb][2] = a1.x; acc[bb][3] = a1.y;
            }
        }

        // recurrent GEMM, weights register-double-buffered one k ahead
        const float* wbase = wdir + p * 8;
        ulonglong2 u0c = reinterpret_cast<const ulonglong2*>(wbase)[0];
        ulonglong2 u1c = reinterpret_cast<const ulonglong2*>(wbase)[1];
#pragma unroll 4
        for (int k = 0; k < HID; ++k) {
            ulonglong2 u0n, u1n;
            if (k < HID - 1) {
                const ulonglong2* wr =
                    reinterpret_cast<const ulonglong2*>(wbase + (size_t)(k + 1) * GATES);
                u0n = wr[0]; u1n = wr[1];
            }
            const float* hrow = &hs[k * BPAD + bg * 16];
            float4 hv0 = *reinterpret_cast<const float4*>(hrow);
            float4 hv1 = *reinterpret_cast<const float4*>(hrow + 4);
            float4 hv2 = *reinterpret_cast<const float4*>(hrow + 8);
            float4 hv3 = *reinterpret_cast<const float4*>(hrow + 12);
            float hf[16] = {hv0.x,hv0.y,hv0.z,hv0.w, hv1.x,hv1.y,hv1.z,hv1.w,
                            hv2.x,hv2.y,hv2.z,hv2.w, hv3.x,hv3.y,hv3.z,hv3.w};
#pragma unroll
            for (int bb = 0; bb < 16; ++bb) {
                ull hv = pack_dup(hf[bb]);
                fma2(acc[bb][0], hv, u0c.x); fma2(acc[bb][1], hv, u0c.y);
                fma2(acc[bb][2], hv, u1c.x); fma2(acc[bb][3], hv, u1c.y);
            }
            u0c = u0n; u1c = u1n;
        }
        __syncthreads();   // all reads of hs done

#pragma unroll
        for (int bb = 0; bb < 16; ++bb) {
            float i0, i1, f0, f1, g0, g1, o0, o1, cc0, cc1;
            unpack2(acc[bb][0], i0, i1); unpack2(acc[bb][1], f0, f1);
            unpack2(acc[bb][2], g0, g1); unpack2(acc[bb][3], o0, o1);
            unpack2(c2[bb], cc0, cc1);
            cc0 = sigf(f0) * cc0 + sigf(i0) * tanhf_(g0);
            cc1 = sigf(f1) * cc1 + sigf(i1) * tanhf_(g1);
            float h0 = sigf(o0) * tanhf_(cc0);
            float h1 = sigf(o1) * tanhf_(cc1);
            c2[bb] = pack2(cc0, cc1);
            int b = bg * 16 + bb;
            hs[(hc0)     * BPAD + b] = h0;
            hs[(hc0 + 1) * BPAD + b] = h1;
            *reinterpret_cast<float2*>(
                &y[((size_t)(b0 + b) * SEQ + t) * 256 + dir * 128 + hc0]) = make_float2(h0, h1);
        }
        if (is_layer0 && s < SEQ - 1) {
            int tn = dir ? (SEQ - 2 - s) : (s + 1);
            for (int i = tid; i < BT * INP; i += 256) {
                int b = i / INP, q = i % INP;
                xsm[b][q] = x[((size_t)(b0 + b) * SEQ + tn) * INP + q];
            }
        }
        __syncthreads();   // hs / xsm ready for next step
    }
}

__global__ void final_kernel(const float* __restrict__ y, const float* __restrict__ wout,
                             const float* __restrict__ bout, float* __restrict__ out)
{
    const int b = blockIdx.x;
    const int tid = threadIdx.x;
    const float* yr = y + (size_t)b * 15360;
    float s0 = 0.f, s1 = 0.f;
    for (int j = tid * 4; j < 15360; j += 128 * 4) {
        float4 v = *reinterpret_cast<const float4*>(&yr[j]);
        v.x = fmaxf(v.x, 0.f); v.y = fmaxf(v.y, 0.f);
        v.z = fmaxf(v.z, 0.f); v.w = fmaxf(v.w, 0.f);
        float4 w0 = __ldg(reinterpret_cast<const float4*>(&wout[j]));
        float4 w1 = __ldg(reinterpret_cast<const float4*>(&wout[15360 + j]));
        s0 += v.x * w0.x + v.y * w0.y + v.z * w0.z + v.w * w0.w;
        s1 += v.x * w1.x + v.y * w1.y + v.z * w1.z + v.w * w1.w;
    }
#pragma unroll
    for (int off = 16; off > 0; off >>= 1) {
        s0 += __shfl_down_sync(0xffffffffu, s0, off);
        s1 += __shfl_down_sync(0xffffffffu, s1, off);
    }
    __shared__ float r0[4], r1[4];
    int wid = tid >> 5;
    if ((tid & 31) == 0) { r0[wid] = s0; r1[wid] = s1; }
    __syncthreads();
    if (tid == 0) {
        out[(size_t)b * 2 + 0] = r0[0] + r0[1] + r0[2] + r0[3] + __ldg(&bout[0]);
        out[(size_t)b * 2 + 1] = r1[0] + r1[1] + r1[2] + r1[3] + __ldg(&bout[1]);
    }
}

extern "C" void kernel_launch(void* const* d_in, const int* in_sizes, int n_in,
                              void* d_out, int out_size) {
    const float* x = (const float*)d_in[0];
    WPtrs P;
    for (int i = 0; i < 6; i++) {
        P.w_ih[i] = (const float*)d_in[1 + 4 * i];
        P.w_hh[i] = (const float*)d_in[2 + 4 * i];
        P.b_ih[i] = (const float*)d_in[3 + 4 * i];
        P.b_hh[i] = (const float*)d_in[4 + 4 * i];
    }
    const float* w_out = (const float*)d_in[25];
    const float* b_out = (const float*)d_in[26];
    float* out = (float*)d_out;

    float *xp, *y0, *y1, *whhP, *w0P; uint4* bfrag;
    cudaGetSymbolAddress((void**)&xp,    g_xp);
    cudaGetSymbolAddress((void**)&y0,    g_y0);
    cudaGetSymbolAddress((void**)&y1,    g_y1);
    cudaGetSymbolAddress((void**)&whhP,  g_whhP);
    cudaGetSymbolAddress((void**)&w0P,   g_w0P);
    cudaGetSymbolAddress((void**)&bfrag, g_bfrag);

    prep_whhP<<<(6 * HID * GATES + 255) / 256, 256>>>(P, whhP);       // 0
    prep_w0P<<<(2 * INP * GATES + 255) / 256, 256>>>(P, w0P);         // 1
    prep_bfrag<<<(BF_TOTAL + 255) / 256, 256>>>(P, bfrag);            // 2

    dim3 rgrid(BATCH / BT, 2);          // (64, 2)
    dim3 ggrid(MROWS / 128, GATES / 128, 2);

    lstm_rec_kernel<<<rgrid, 256>>>(nullptr, x, w0P,                  // 3
                                    P.b_ih[0], P.b_hh[0], P.b_ih[1], P.b_hh[1],
                                    whhP + 0 * (size_t)HID * GATES, whhP + 1 * (size_t)HID * GATES,
                                    y0, 1);
    gemm_mma<<<ggrid, 256>>>(y0, bfrag,                               // 4
                             P.b_ih[2], P.b_hh[2], P.b_ih[3], P.b_hh[3], xp);
    lstm_rec_kernel<<<rgrid, 256>>>(xp, nullptr, nullptr,             // 5  (ncu -s 5)
                                    P.b_ih[2], P.b_hh[2], P.b_ih[3], P.b_hh[3],
                                    whhP + 2 * (size_t)HID * GATES, whhP + 3 * (size_t)HID * GATES,
                                    y1, 0);
    gemm_mma<<<ggrid, 256>>>(y1, bfrag + BF_PER_LAYER,                // 6
                             P.b_ih[4], P.b_hh[4], P.b_ih[5], P.b_hh[5], xp);
    lstm_rec_kernel<<<rgrid, 256>>>(xp, nullptr, nullptr,             // 7
                                    P.b_ih[4], P.b_hh[4], P.b_ih[5], P.b_hh[5],
                                    whhP + 4 * (size_t)HID * GATES, whhP + 5 * (size_t)HID * GATES,
                                    y0, 0);
    final_kernel<<<BATCH, 128>>>(y0, w_out, b_out, out);              // 8
}

// round 9
// speedup vs baseline: 1.6832x; 1.6613x over previous
#include <cuda_runtime.h>
#include <cuda_bf16.h>
#include <cstdint>
#include <cstddef>

#define BATCH 4096
#define SEQ   60
#define INP   13
#define HID   128
#define GATES 512
#define MROWS (BATCH*SEQ)
#define BT    64

#define BF_PER_LAYER (2*16*64*32)      // gemm b-frag table (uint4), per layer
#define BF_TOTAL     (2*BF_PER_LAYER)
#define WF_PER_W     (8*8*8*32)        // whh frag per (layer,dir): kc*wn*i*lane
#define WF_TOTAL     (6*WF_PER_W)

// rec smem: hA [2][8][64][24] bf16 = 49152 B; w0sm 13*512*4 = 26624; xsm 64*16*4 = 4096
#define HA_BYTES   49152
#define W0_BYTES   26624
#define XS_BYTES   4096
#define SMEM_REC   (HA_BYTES + W0_BYTES + XS_BYTES)

__device__ float g_xp[(size_t)2 * MROWS * GATES];
__device__ float g_y0[(size_t)MROWS * 256];
__device__ float g_y1[(size_t)MROWS * 256];
__device__ float g_w0T[2 * INP * GATES];      // natural [dir][q][512]
__device__ uint4 g_bfrag[BF_TOTAL];           // gemm weights (layers 1,2)
__device__ uint4 g_wfrag[WF_TOTAL];           // whh fragments, all 6

__device__ __forceinline__ float sigf(float x) { return __fdividef(1.f, 1.f + __expf(-x)); }
__device__ __forceinline__ float tanhf_(float x) {
    float ax = fabsf(x); float e = __expf(-2.f * ax);
    return copysignf(__fdividef(1.f - e, 1.f + e), x);
}
__device__ __forceinline__ uint32_t pack_bf2(float a, float b) {
    __nv_bfloat162 t = __floats2bfloat162_rn(a, b);
    return *reinterpret_cast<uint32_t*>(&t);
}
__device__ __forceinline__ void split_hl(float v, float& hi, float& lo) {
    __nv_bfloat16 h = __float2bfloat16_rn(v);
    hi = __bfloat162float(h);
    lo = v - hi;
}
__device__ __forceinline__ void mma16816(float c[4], const uint32_t a[4],
                                         uint32_t b0, uint32_t b1) {
    asm volatile("mma.sync.aligned.m16n8k16.row.col.f32.bf16.bf16.f32 "
                 "{%0,%1,%2,%3}, {%4,%5,%6,%7}, {%8,%9}, {%0,%1,%2,%3};"
                 : "+f"(c[0]), "+f"(c[1]), "+f"(c[2]), "+f"(c[3])
                 : "r"(a[0]), "r"(a[1]), "r"(a[2]), "r"(a[3]), "r"(b0), "r"(b1));
}
__device__ __forceinline__ void ldmx4(uint32_t r[4], const void* p) {
    uint32_t addr = (uint32_t)__cvta_generic_to_shared(p);
    asm volatile("ldmatrix.sync.aligned.m8n8.x4.shared.b16 {%0,%1,%2,%3}, [%4];"
                 : "=r"(r[0]), "=r"(r[1]), "=r"(r[2]), "=r"(r[3]) : "r"(addr));
}

struct WPtrs {
    const float* w_ih[6];
    const float* w_hh[6];
    const float* b_ih[6];
    const float* b_hh[6];
};

// ---- prep: w0 transpose (natural [dir][q][512]) ----
__global__ void prep_w0T(WPtrs P, float* __restrict__ dst) {
    int idx = blockIdx.x * 256 + threadIdx.x;
    if (idx >= 2 * INP * GATES) return;
    int d = idx / (INP * GATES), rem = idx % (INP * GATES);
    int q = rem / GATES, j = rem % GATES;
    dst[idx] = P.w_ih[d][j * INP + q];
}

// ---- prep: gemm b-fragments (layers 1,2) — unchanged, validated ----
__global__ void prep_bfrag(WPtrs P, uint4* __restrict__ bf) {
    int idx = blockIdx.x * 256 + threadIdx.x;
    if (idx >= BF_TOTAL) return;
    int lane = idx & 31;
    int n8   = (idx >> 5) & 63;
    int kc   = (idx >> 11) & 15;
    int dir  = (idx >> 15) & 1;
    int layer = idx >> 16;
    const float* W = P.w_ih[2 + layer * 2 + dir];
    int n = n8 * 8 + (lane >> 2);
    int kb = kc * 16 + (lane & 3) * 2;
    float v00 = W[n * 256 + kb + 0], v01 = W[n * 256 + kb + 1];
    float v10 = W[n * 256 + kb + 8], v11 = W[n * 256 + kb + 9];
    float h00, l00, h01, l01, h10, l10, h11, l11;
    split_hl(v00, h00, l00); split_hl(v01, h01, l01);
    split_hl(v10, h10, l10); split_hl(v11, h11, l11);
    uint4 o;
    o.x = pack_bf2(h00, h01); o.y = pack_bf2(h10, h11);
    o.z = pack_bf2(l00, l01); o.w = pack_bf2(l10, l11);
    bf[idx] = o;
}

// ---- prep: whh fragments, gate-interleaved warp groups ----
// table [w(6)][kc(8)][wn(8)][i(8)][lane(32)]; group i -> gate g=i>>1, blk=i&1
__global__ void prep_wfrag(WPtrs P, uint4* __restrict__ wf) {
    int idx = blockIdx.x * 256 + threadIdx.x;
    if (idx >= WF_TOTAL) return;
    int lane = idx & 31;
    int i    = (idx >> 5) & 7;
    int wn   = (idx >> 8) & 7;
    int kc   = (idx >> 11) & 7;
    int w    = idx >> 14;
    int g = i >> 1, blk = i & 1;
    int n = (g * 16 + wn * 2 + blk) * 8 + (lane >> 2);
    int kb = kc * 16 + (lane & 3) * 2;
    const float* W = P.w_hh[w];
    float v00 = W[n * HID + kb + 0], v01 = W[n * HID + kb + 1];
    float v10 = W[n * HID + kb + 8], v11 = W[n * HID + kb + 9];
    float h00, l00, h01, l01, h10, l10, h11, l11;
    split_hl(v00, h00, l00); split_hl(v01, h01, l01);
    split_hl(v10, h10, l10); split_hl(v11, h11, l11);
    uint4 o;
    o.x = pack_bf2(h00, h01); o.y = pack_bf2(h10, h11);
    o.z = pack_bf2(l00, l01); o.w = pack_bf2(l10, l11);
    wf[idx] = o;
}

// ---- split-bf16 tensor-core projection GEMM (R5-proven, natural epilogue) ----
__global__ __launch_bounds__(256, 1)
void gemm_mma(const float* __restrict__ A,
              const uint4* __restrict__ bfrag,
              const float* __restrict__ bihF, const float* __restrict__ bhhF,
              const float* __restrict__ bihB, const float* __restrict__ bhhB,
              float* __restrict__ xp)
{
    const int dir = blockIdx.z;
    const int m0  = blockIdx.x * 128;
    const int n0  = blockIdx.y * 128;
    const int tid = threadIdx.x;
    const int lane = tid & 31, wid = tid >> 5;
    const int wm = wid & 3, wn = wid >> 2;
    const float* bih = dir ? bihB : bihF;
    const float* bhh = dir ? bhhB : bhhF;

    __shared__ __align__(16) uint16_t Asm[2][128][24];

    float acc[2][8][4];
#pragma unroll
    for (int a = 0; a < 2; a++)
#pragma unroll
        for (int b = 0; b < 8; b++)
#pragma unroll
            for (int c = 0; c < 4; c++) acc[a][b][c] = 0.f;

    const int lrow0 = wm * 32 + (lane & 7) + ((lane >> 3) & 1) * 8;
    const int lkb   = (lane & 16) ? 8 : 0;
    const int arow = tid & 127;
    const int ach  = tid >> 7;

    for (int kc = 0; kc < 16; ++kc) {
        {
            const float4* src = reinterpret_cast<const float4*>(
                &A[(size_t)(m0 + arow) * 256 + kc * 16 + ach * 8]);
            float4 v0 = src[0], v1 = src[1];
            float hv[8], lv[8];
            split_hl(v0.x, hv[0], lv[0]); split_hl(v0.y, hv[1], lv[1]);
            split_hl(v0.z, hv[2], lv[2]); split_hl(v0.w, hv[3], lv[3]);
            split_hl(v1.x, hv[4], lv[4]); split_hl(v1.y, hv[5], lv[5]);
            split_hl(v1.z, hv[6], lv[6]); split_hl(v1.w, hv[7], lv[7]);
            uint4 ph, pl;
            ph.x = pack_bf2(hv[0], hv[1]); ph.y = pack_bf2(hv[2], hv[3]);
            ph.z = pack_bf2(hv[4], hv[5]); ph.w = pack_bf2(hv[6], hv[7]);
            pl.x = pack_bf2(lv[0], lv[1]); pl.y = pack_bf2(lv[2], lv[3]);
            pl.z = pack_bf2(lv[4], lv[5]); pl.w = pack_bf2(lv[6], lv[7]);
            *reinterpret_cast<uint4*>(&Asm[0][arow][ach * 8]) = ph;
            *reinterpret_cast<uint4*>(&Asm[1][arow][ach * 8]) = pl;
        }
        __syncthreads();

        uint4 bf[8];
        const int nbase = blockIdx.y * 16 + wn * 8;
#pragma unroll
        for (int i = 0; i < 8; ++i)
            bf[i] = bfrag[(((size_t)(dir * 16 + kc) * 64) + nbase + i) * 32 + lane];

        uint32_t ah[2][4], al[2][4];
#pragma unroll
        for (int ms = 0; ms < 2; ++ms) {
            ldmx4(ah[ms], &Asm[0][lrow0 + ms * 16][lkb]);
            ldmx4(al[ms], &Asm[1][lrow0 + ms * 16][lkb]);
        }

#pragma unroll
        for (int i = 0; i < 8; ++i) {
#pragma unroll
            for (int ms = 0; ms < 2; ++ms) {
                mma16816(acc[ms][i], ah[ms], bf[i].x, bf[i].y);
                mma16816(acc[ms][i], ah[ms], bf[i].z, bf[i].w);
                mma16816(acc[ms][i], al[ms], bf[i].x, bf[i].y);
            }
        }
        __syncthreads();
    }

    const int g  = lane >> 2;
    const int t2 = (lane & 3) * 2;
#pragma unroll
    for (int ms = 0; ms < 2; ++ms) {
#pragma unroll
        for (int i = 0; i < 8; ++i) {
            int n = n0 + wn * 64 + i * 8 + t2;
            float b0 = bih[n] + bhh[n];
            float b1 = bih[n + 1] + bhh[n + 1];
            size_t r0 = (size_t)dir * MROWS + m0 + wm * 32 + ms * 16 + g;
            *reinterpret_cast<float2*>(&xp[r0 * 512 + n]) =
                make_float2(acc[ms][i][0] + b0, acc[ms][i][1] + b1);
            *reinterpret_cast<float2*>(&xp[(r0 + 8) * 512 + n]) =
                make_float2(acc[ms][i][2] + b0, acc[ms][i][3] + b1);
        }
    }
}

// ---- tensor-core recurrence: BT=64, gate-interleaved warp n-groups ----
__global__ __launch_bounds__(256, 1)
void lstm_rec_mma(const float* __restrict__ xp, const float* __restrict__ x,
                  const float* __restrict__ w0T,
                  const float* __restrict__ bihF, const float* __restrict__ bhhF,
                  const float* __restrict__ bihB, const float* __restrict__ bhhB,
                  const uint4* __restrict__ fragF, const uint4* __restrict__ fragB,
                  float* __restrict__ y, int is_layer0)
{
    extern __shared__ __align__(16) char sm[];
    __nv_bfloat16* hA = reinterpret_cast<__nv_bfloat16*>(sm);      // [2][8][64][24]
    uint32_t* hA32 = reinterpret_cast<uint32_t*>(sm);
    float* w0sm = reinterpret_cast<float*>(sm + HA_BYTES);          // [13][512]
    float (*xsm)[16] = reinterpret_cast<float(*)[16]>(sm + HA_BYTES + W0_BYTES);

    const int dir = blockIdx.y;
    const int b0  = blockIdx.x * BT;
    const int tid = threadIdx.x;
    const int lane = tid & 31, wn = tid >> 5;
    const uint4* frag = dir ? fragB : fragF;
    const float* bi = dir ? bihB : bihF;
    const float* bh = dir ? bhhB : bhhF;

    // zero hA (h = 0)
    for (int i = tid; i < HA_BYTES / 4; i += 256) hA32[i] = 0u;

    // thread's 16 gate columns: group i -> j(i), e in {0,1}
    int jcol[8];
#pragma unroll
    for (int i = 0; i < 8; ++i)
        jcol[i] = ((i >> 1) * 128) + (wn * 2 + (i & 1)) * 8 + (lane & 3) * 2;

    float biasv[8][2];
    if (is_layer0) {
        for (int i = tid; i < INP * GATES; i += 256)
            w0sm[i] = w0T[(size_t)dir * INP * GATES + i];
        int t0 = dir ? SEQ - 1 : 0;
        for (int i = tid; i < BT * INP; i += 256) {
            int b = i / INP, q = i % INP;
            xsm[b][q] = x[((size_t)(b0 + b) * SEQ + t0) * INP + q];
        }
#pragma unroll
        for (int i = 0; i < 8; ++i) {
            biasv[i][0] = bi[jcol[i]] + bh[jcol[i]];
            biasv[i][1] = bi[jcol[i] + 1] + bh[jcol[i] + 1];
        }
    }

    float c2[32];
#pragma unroll
    for (int i = 0; i < 32; ++i) c2[i] = 0.f;
    __syncthreads();

    const size_t xpdir = (size_t)dir * MROWS * GATES;
    const int rowsel = (lane & 7) + ((lane >> 3) & 1) * 8;
    const int lkb = (lane & 16) ? 8 : 0;

    for (int s = 0; s < SEQ; ++s) {
        const int t = dir ? (SEQ - 1 - s) : s;
        float acc[4][8][4];

        if (is_layer0) {
#pragma unroll
            for (int mt = 0; mt < 4; ++mt)
#pragma unroll
                for (int i = 0; i < 8; ++i) {
                    acc[mt][i][0] = biasv[i][0]; acc[mt][i][1] = biasv[i][1];
                    acc[mt][i][2] = biasv[i][0]; acc[mt][i][3] = biasv[i][1];
                }
            for (int q = 0; q < INP; ++q) {
                float2 w[8];
#pragma unroll
                for (int i = 0; i < 8; ++i)
                    w[i] = *reinterpret_cast<const float2*>(&w0sm[q * GATES + jcol[i]]);
#pragma unroll
                for (int mt = 0; mt < 4; ++mt)
#pragma unroll
                    for (int r8 = 0; r8 < 2; ++r8) {
                        float xv = xsm[mt * 16 + r8 * 8 + (lane >> 2)][q];
#pragma unroll
                        for (int i = 0; i < 8; ++i) {
                            acc[mt][i][r8 * 2]     += xv * w[i].x;
                            acc[mt][i][r8 * 2 + 1] += xv * w[i].y;
                        }
                    }
            }
        } else {
#pragma unroll
            for (int mt = 0; mt < 4; ++mt)
#pragma unroll
                for (int r8 = 0; r8 < 2; ++r8) {
                    int m = b0 + mt * 16 + r8 * 8 + (lane >> 2);
                    const float* xr = xp + xpdir + ((size_t)m * SEQ + t) * GATES;
#pragma unroll
                    for (int i = 0; i < 8; ++i) {
                        float2 v = *reinterpret_cast<const float2*>(&xr[jcol[i]]);
                        acc[mt][i][r8 * 2] = v.x; acc[mt][i][r8 * 2 + 1] = v.y;
                    }
                }
        }

        // K loop: 8 chunks of 16 hidden
#pragma unroll 1
        for (int kc = 0; kc < 8; ++kc) {
            uint4 bf[8];
#pragma unroll
            for (int i = 0; i < 8; ++i)
                bf[i] = frag[(((kc * 8 + wn) * 8) + i) * 32 + lane];
#pragma unroll
            for (int mt = 0; mt < 4; ++mt) {
                uint32_t ah[4], al[4];
                ldmx4(ah, &hA[((0 * 8 + kc) * 64 + mt * 16 + rowsel) * 24 + lkb]);
                ldmx4(al, &hA[((1 * 8 + kc) * 64 + mt * 16 + rowsel) * 24 + lkb]);
#pragma unroll
                for (int i = 0; i < 8; ++i) mma16816(acc[mt][i], ah, bf[i].x, bf[i].y);
#pragma unroll
                for (int i = 0; i < 8; ++i) mma16816(acc[mt][i], ah, bf[i].z, bf[i].w);
#pragma unroll
                for (int i = 0; i < 8; ++i) mma16816(acc[mt][i], al, bf[i].x, bf[i].y);
            }
        }
        __syncthreads();   // all ldmatrix reads of hA done

        // epilogue: gates -> c,h ; h -> y (fp32) + hA (bf16 hi/lo)
#pragma unroll
        for (int mt = 0; mt < 4; ++mt)
#pragma unroll
            for (int r8 = 0; r8 < 2; ++r8)
#pragma unroll
                for (int blk = 0; blk < 2; ++blk) {
                    int c0i = r8 * 2;
                    float ii0 = acc[mt][blk][c0i],     ii1 = acc[mt][blk][c0i + 1];
                    float ff0 = acc[mt][2 + blk][c0i], ff1 = acc[mt][2 + blk][c0i + 1];
                    float gg0 = acc[mt][4 + blk][c0i], gg1 = acc[mt][4 + blk][c0i + 1];
                    float oo0 = acc[mt][6 + blk][c0i], oo1 = acc[mt][6 + blk][c0i + 1];
                    int ci = ((mt * 2 + r8) * 2 + blk) * 2;
                    float cc0 = c2[ci], cc1 = c2[ci + 1];
                    cc0 = sigf(ff0) * cc0 + sigf(ii0) * tanhf_(gg0);
                    cc1 = sigf(ff1) * cc1 + sigf(ii1) * tanhf_(gg1);
                    float h0 = sigf(oo0) * tanhf_(cc0);
                    float h1 = sigf(oo1) * tanhf_(cc1);
                    c2[ci] = cc0; c2[ci + 1] = cc1;
                    int row = mt * 16 + r8 * 8 + (lane >> 2);
                    int hc0 = wn * 16 + blk * 8 + (lane & 3) * 2;
                    *reinterpret_cast<float2*>(
                        &y[((size_t)(b0 + row) * SEQ + t) * 256 + dir * 128 + hc0]) =
                        make_float2(h0, h1);
                    float h0h, h0l, h1h, h1l;
                    split_hl(h0, h0h, h0l); split_hl(h1, h1h, h1l);
                    int base = row * 12 + blk * 4 + (lane & 3);
                    hA32[((0 * 8 + wn) * 64) * 12 + base] = pack_bf2(h0h, h1h);
                    hA32[((1 * 8 + wn) * 64) * 12 + base] = pack_bf2(h0l, h1l);
                }
        if (is_layer0 && s < SEQ - 1) {
            int tn = dir ? (SEQ - 2 - s) : (s + 1);
            for (int i = tid; i < BT * INP; i += 256) {
                int b = i / INP, q = i % INP;
                xsm[b][q] = x[((size_t)(b0 + b) * SEQ + tn) * INP + q];
            }
        }
        __syncthreads();   // hA / xsm ready for next step
    }
}

__global__ void final_kernel(const float* __restrict__ y, const float* __restrict__ wout,
                             const float* __restrict__ bout, float* __restrict__ out)
{
    const int b = blockIdx.x;
    const int tid = threadIdx.x;
    const float* yr = y + (size_t)b * 15360;
    float s0 = 0.f, s1 = 0.f;
    for (int j = tid * 4; j < 15360; j += 128 * 4) {
        float4 v = *reinterpret_cast<const float4*>(&yr[j]);
        v.x = fmaxf(v.x, 0.f); v.y = fmaxf(v.y, 0.f);
        v.z = fmaxf(v.z, 0.f); v.w = fmaxf(v.w, 0.f);
        float4 w0 = __ldg(reinterpret_cast<const float4*>(&wout[j]));
        float4 w1 = __ldg(reinterpret_cast<const float4*>(&wout[15360 + j]));
        s0 += v.x * w0.x + v.y * w0.y + v.z * w0.z + v.w * w0.w;
        s1 += v.x * w1.x + v.y * w1.y + v.z * w1.z + v.w * w1.w;
    }
#pragma unroll
    for (int off = 16; off > 0; off >>= 1) {
        s0 += __shfl_down_sync(0xffffffffu, s0, off);
        s1 += __shfl_down_sync(0xffffffffu, s1, off);
    }
    __shared__ float r0[4], r1[4];
    int wid = tid >> 5;
    if ((tid & 31) == 0) { r0[wid] = s0; r1[wid] = s1; }
    __syncthreads();
    if (tid == 0) {
        out[(size_t)b * 2 + 0] = r0[0] + r0[1] + r0[2] + r0[3] + __ldg(&bout[0]);
        out[(size_t)b * 2 + 1] = r1[0] + r1[1] + r1[2] + r1[3] + __ldg(&bout[1]);
    }
}

extern "C" void kernel_launch(void* const* d_in, const int* in_sizes, int n_in,
                              void* d_out, int out_size) {
    const float* x = (const float*)d_in[0];
    WPtrs P;
    for (int i = 0; i < 6; i++) {
        P.w_ih[i] = (const float*)d_in[1 + 4 * i];
        P.w_hh[i] = (const float*)d_in[2 + 4 * i];
        P.b_ih[i] = (const float*)d_in[3 + 4 * i];
        P.b_hh[i] = (const float*)d_in[4 + 4 * i];
    }
    const float* w_out = (const float*)d_in[25];
    const float* b_out = (const float*)d_in[26];
    float* out = (float*)d_out;

    float *xp, *y0, *y1, *w0T; uint4 *bfrag, *wfrag;
    cudaGetSymbolAddress((void**)&xp,    g_xp);
    cudaGetSymbolAddress((void**)&y0,    g_y0);
    cudaGetSymbolAddress((void**)&y1,    g_y1);
    cudaGetSymbolAddress((void**)&w0T,   g_w0T);
    cudaGetSymbolAddress((void**)&bfrag, g_bfrag);
    cudaGetSymbolAddress((void**)&wfrag, g_wfrag);

    cudaFuncSetAttribute(lstm_rec_mma,
                         cudaFuncAttributeMaxDynamicSharedMemorySize, SMEM_REC);

    prep_w0T<<<(2 * INP * GATES + 255) / 256, 256>>>(P, w0T);          // 0
    prep_bfrag<<<(BF_TOTAL + 255) / 256, 256>>>(P, bfrag);             // 1
    prep_wfrag<<<(WF_TOTAL + 255) / 256, 256>>>(P, wfrag);             // 2

    dim3 rgrid(BATCH / BT, 2);          // (64, 2)
    dim3 ggrid(MROWS / 128, GATES / 128, 2);

    lstm_rec_mma<<<rgrid, 256, SMEM_REC>>>(nullptr, x, w0T,            // 3
                                    P.b_ih[0], P.b_hh[0], P.b_ih[1], P.b_hh[1],
                                    wfrag + 0 * (size_t)WF_PER_W, wfrag + 1 * (size_t)WF_PER_W,
                                    y0, 1);
    gemm_mma<<<ggrid, 256>>>(y0, bfrag,                                // 4
                             P.b_ih[2], P.b_hh[2], P.b_ih[3], P.b_hh[3], xp);
    lstm_rec_mma<<<rgrid, 256, SMEM_REC>>>(xp, nullptr, w0T,           // 5 (ncu -s 5)
                                    P.b_ih[2], P.b_hh[2], P.b_ih[3], P.b_hh[3],
                                    wfrag + 2 * (size_t)WF_PER_W, wfrag + 3 * (size_t)WF_PER_W,
                                    y1, 0);
    gemm_mma<<<ggrid, 256>>>(y1, bfrag + BF_PER_LAYER,                 // 6
                             P.b_ih[4], P.b_hh[4], P.b_ih[5], P.b_hh[5], xp);
    lstm_rec_mma<<<rgrid, 256, SMEM_REC>>>(xp, nullptr, w0T,           // 7
                                    P.b_ih[4], P.b_hh[4], P.b_ih[5], P.b_hh[5],
                                    wfrag + 4 * (size_t)WF_PER_W, wfrag + 5 * (size_t)WF_PER_W,
                                    y0, 0);
    final_kernel<<<BATCH, 128>>>(y0, w_out, b_out, out);               // 8
}

// round 10
// speedup vs baseline: 2.0256x; 1.2034x over previous
#include <cuda_runtime.h>
#include <cuda_bf16.h>
#include <cstdint>
#include <cstddef>

#define BATCH 4096
#define SEQ   60
#define INP   13
#define HID   128
#define GATES 512
#define MROWS (BATCH*SEQ)
#define BT    32

#define BF_PER_LAYER (2*16*64*32)      // gemm b-frag table (uint4), per layer
#define BF_TOTAL     (2*BF_PER_LAYER)
#define WF_PER_W     (8*8*8*32)        // whh frag per (layer,dir)
#define WF_TOTAL     (6*WF_PER_W)
#define AF_TOTAL     ((size_t)(MROWS/16) * 16 * 32 * 2)   // uint4 count

// rec smem: hA [2][8][32][24] bf16 = 24576 B; w0sm 13*512*4 = 26624; xsm 32*16*4 = 2048
#define HA_BYTES   24576
#define W0_BYTES   26624
#define XS_BYTES   2048
#define SMEM_REC   (HA_BYTES + W0_BYTES + XS_BYTES)

__device__ float g_xp[(size_t)2 * MROWS * GATES];
__device__ float g_y0[(size_t)MROWS * 256];
__device__ float g_y1[(size_t)MROWS * 256];
__device__ float g_w0T[2 * INP * GATES];
__device__ uint4 g_bfrag[BF_TOTAL];
__device__ uint4 g_wfrag[WF_TOTAL];
__device__ uint4 g_afrag[AF_TOTAL];

__device__ __forceinline__ float sigf(float x) { return __fdividef(1.f, 1.f + __expf(-x)); }
__device__ __forceinline__ float tanhf_(float x) {
    float ax = fabsf(x); float e = __expf(-2.f * ax);
    return copysignf(__fdividef(1.f - e, 1.f + e), x);
}
__device__ __forceinline__ uint32_t pack_bf2(float a, float b) {
    __nv_bfloat162 t = __floats2bfloat162_rn(a, b);
    return *reinterpret_cast<uint32_t*>(&t);
}
__device__ __forceinline__ void split_hl(float v, float& hi, float& lo) {
    __nv_bfloat16 h = __float2bfloat16_rn(v);
    hi = __bfloat162float(h);
    lo = v - hi;
}
__device__ __forceinline__ void mma16816(float c[4], const uint32_t a[4],
                                         uint32_t b0, uint32_t b1) {
    asm volatile("mma.sync.aligned.m16n8k16.row.col.f32.bf16.bf16.f32 "
                 "{%0,%1,%2,%3}, {%4,%5,%6,%7}, {%8,%9}, {%0,%1,%2,%3};"
                 : "+f"(c[0]), "+f"(c[1]), "+f"(c[2]), "+f"(c[3])
                 : "r"(a[0]), "r"(a[1]), "r"(a[2]), "r"(a[3]), "r"(b0), "r"(b1));
}
__device__ __forceinline__ void mma16816u(float c[4], const uint4& a,
                                          uint32_t b0, uint32_t b1) {
    asm volatile("mma.sync.aligned.m16n8k16.row.col.f32.bf16.bf16.f32 "
                 "{%0,%1,%2,%3}, {%4,%5,%6,%7}, {%8,%9}, {%0,%1,%2,%3};"
                 : "+f"(c[0]), "+f"(c[1]), "+f"(c[2]), "+f"(c[3])
                 : "r"(a.x), "r"(a.y), "r"(a.z), "r"(a.w), "r"(b0), "r"(b1));
}
__device__ __forceinline__ void ldmx4(uint32_t r[4], const void* p) {
    uint32_t addr = (uint32_t)__cvta_generic_to_shared(p);
    asm volatile("ldmatrix.sync.aligned.m8n8.x4.shared.b16 {%0,%1,%2,%3}, [%4];"
                 : "=r"(r[0]), "=r"(r[1]), "=r"(r[2]), "=r"(r[3]) : "r"(addr));
}

struct WPtrs {
    const float* w_ih[6];
    const float* w_hh[6];
    const float* b_ih[6];
    const float* b_hh[6];
};

__global__ void prep_w0T(WPtrs P, float* __restrict__ dst) {
    int idx = blockIdx.x * 256 + threadIdx.x;
    if (idx >= 2 * INP * GATES) return;
    int d = idx / (INP * GATES), rem = idx % (INP * GATES);
    int q = rem / GATES, j = rem % GATES;
    dst[idx] = P.w_ih[d][j * INP + q];
}

__global__ void prep_bfrag(WPtrs P, uint4* __restrict__ bf) {
    int idx = blockIdx.x * 256 + threadIdx.x;
    if (idx >= BF_TOTAL) return;
    int lane = idx & 31;
    int n8   = (idx >> 5) & 63;
    int kc   = (idx >> 11) & 15;
    int dir  = (idx >> 15) & 1;
    int layer = idx >> 16;
    const float* W = P.w_ih[2 + layer * 2 + dir];
    int n = n8 * 8 + (lane >> 2);
    int kb = kc * 16 + (lane & 3) * 2;
    float v00 = W[n * 256 + kb + 0], v01 = W[n * 256 + kb + 1];
    float v10 = W[n * 256 + kb + 8], v11 = W[n * 256 + kb + 9];
    float h00, l00, h01, l01, h10, l10, h11, l11;
    split_hl(v00, h00, l00); split_hl(v01, h01, l01);
    split_hl(v10, h10, l10); split_hl(v11, h11, l11);
    uint4 o;
    o.x = pack_bf2(h00, h01); o.y = pack_bf2(h10, h11);
    o.z = pack_bf2(l00, l01); o.w = pack_bf2(l10, l11);
    bf[idx] = o;
}

__global__ void prep_wfrag(WPtrs P, uint4* __restrict__ wf) {
    int idx = blockIdx.x * 256 + threadIdx.x;
    if (idx >= WF_TOTAL) return;
    int lane = idx & 31;
    int i    = (idx >> 5) & 7;
    int wn   = (idx >> 8) & 7;
    int kc   = (idx >> 11) & 7;
    int w    = idx >> 14;
    int g = i >> 1, blk = i & 1;
    int n = (g * 16 + wn * 2 + blk) * 8 + (lane >> 2);
    int kb = kc * 16 + (lane & 3) * 2;
    const float* W = P.w_hh[w];
    float v00 = W[n * HID + kb + 0], v01 = W[n * HID + kb + 1];
    float v10 = W[n * HID + kb + 8], v11 = W[n * HID + kb + 9];
    float h00, l00, h01, l01, h10, l10, h11, l11;
    split_hl(v00, h00, l00); split_hl(v01, h01, l01);
    split_hl(v10, h10, l10); split_hl(v11, h11, l11);
    uint4 o;
    o.x = pack_bf2(h00, h01); o.y = pack_bf2(h10, h11);
    o.z = pack_bf2(l00, l01); o.w = pack_bf2(l10, l11);
    wf[idx] = o;
}

// A [MROWS][256] fp32 -> canonical mma A-fragments (hi,lo interleaved)
__global__ void prep_afrag(const float* __restrict__ A, uint4* __restrict__ af) {
    size_t idx = (size_t)blockIdx.x * 256 + threadIdx.x;
    if (idx >= AF_TOTAL / 2) return;
    int lane = idx & 31;
    int kc   = (idx >> 5) & 15;
    size_t mt = idx >> 9;
    int r = lane >> 2, c = kc * 16 + (lane & 3) * 2;
    const float* A0 = A + (mt * 16 + r) * 256;
    const float* A1 = A0 + 8 * 256;
    float2 v0 = *reinterpret_cast<const float2*>(A0 + c);
    float2 v1 = *reinterpret_cast<const float2*>(A1 + c);
    float2 v2 = *reinterpret_cast<const float2*>(A0 + c + 8);
    float2 v3 = *reinterpret_cast<const float2*>(A1 + c + 8);
    float h0a,l0a,h0b,l0b, h1a,l1a,h1b,l1b, h2a,l2a,h2b,l2b, h3a,l3a,h3b,l3b;
    split_hl(v0.x,h0a,l0a); split_hl(v0.y,h0b,l0b);
    split_hl(v1.x,h1a,l1a); split_hl(v1.y,h1b,l1b);
    split_hl(v2.x,h2a,l2a); split_hl(v2.y,h2b,l2b);
    split_hl(v3.x,h3a,l3a); split_hl(v3.y,h3b,l3b);
    uint4 hi, lo;
    hi.x = pack_bf2(h0a,h0b); hi.y = pack_bf2(h1a,h1b);
    hi.z = pack_bf2(h2a,h2b); hi.w = pack_bf2(h3a,h3b);
    lo.x = pack_bf2(l0a,l0b); lo.y = pack_bf2(l1a,l1b);
    lo.z = pack_bf2(l2a,l2b); lo.w = pack_bf2(l3a,l3b);
    af[idx * 2]     = hi;
    af[idx * 2 + 1] = lo;
}

// ---- sync-free projection GEMM from prefragged A ----
__global__ __launch_bounds__(256)
void gemm_mma2(const uint4* __restrict__ afrag,
               const uint4* __restrict__ bfrag,
               const float* __restrict__ bihF, const float* __restrict__ bhhF,
               const float* __restrict__ bihB, const float* __restrict__ bhhB,
               float* __restrict__ xp)
{
    const int dir = blockIdx.z;
    const int tid = threadIdx.x;
    const int lane = tid & 31, wid = tid >> 5;
    const int wm = wid & 3, wn = wid >> 2;
    const float* bih = dir ? bihB : bihF;
    const float* bhh = dir ? bhhB : bhhF;

    float acc[2][8][4];
#pragma unroll
    for (int a = 0; a < 2; a++)
#pragma unroll
        for (int b = 0; b < 8; b++)
#pragma unroll
            for (int c = 0; c < 4; c++) acc[a][b][c] = 0.f;

    const size_t mtile0 = (size_t)blockIdx.x * 8 + wm * 2;
    const int nbase = blockIdx.y * 16 + wn * 8;

#pragma unroll 4
    for (int kc = 0; kc < 16; ++kc) {
        uint4 ah[2], al[2];
#pragma unroll
        for (int ms = 0; ms < 2; ++ms) {
            size_t base = (((mtile0 + ms) * 16 + kc) * 32 + lane) * 2;
            ah[ms] = afrag[base];
            al[ms] = afrag[base + 1];
        }
        uint4 bf[8];
#pragma unroll
        for (int i = 0; i < 8; ++i)
            bf[i] = bfrag[(((size_t)(dir * 16 + kc) * 64) + nbase + i) * 32 + lane];
#pragma unroll
        for (int i = 0; i < 8; ++i) {
#pragma unroll
            for (int ms = 0; ms < 2; ++ms) {
                mma16816u(acc[ms][i], ah[ms], bf[i].x, bf[i].y);
                mma16816u(acc[ms][i], ah[ms], bf[i].z, bf[i].w);
                mma16816u(acc[ms][i], al[ms], bf[i].x, bf[i].y);
            }
        }
    }

    const int m0 = blockIdx.x * 128;
    const int n0 = blockIdx.y * 128;
    const int g  = lane >> 2;
    const int t2 = (lane & 3) * 2;
#pragma unroll
    for (int ms = 0; ms < 2; ++ms) {
#pragma unroll
        for (int i = 0; i < 8; ++i) {
            int n = n0 + wn * 64 + i * 8 + t2;
            float b0 = bih[n] + bhh[n];
            float b1 = bih[n + 1] + bhh[n + 1];
            size_t r0 = (size_t)dir * MROWS + m0 + (wm * 2 + ms) * 16 + g;
            *reinterpret_cast<float2*>(&xp[r0 * 512 + n]) =
                make_float2(acc[ms][i][0] + b0, acc[ms][i][1] + b1);
            *reinterpret_cast<float2*>(&xp[(r0 + 8) * 512 + n]) =
                make_float2(acc[ms][i][2] + b0, acc[ms][i][3] + b1);
        }
    }
}

// ---- tensor-core recurrence: BT=32, 2 CTAs/SM ----
__global__ __launch_bounds__(256, 2)
void lstm_rec_mma(const float* __restrict__ xp, const float* __restrict__ x,
                  const float* __restrict__ w0T,
                  const float* __restrict__ bihF, const float* __restrict__ bhhF,
                  const float* __restrict__ bihB, const float* __restrict__ bhhB,
                  const uint4* __restrict__ fragF, const uint4* __restrict__ fragB,
                  float* __restrict__ y, int is_layer0)
{
    extern __shared__ __align__(16) char sm[];
    __nv_bfloat16* hA = reinterpret_cast<__nv_bfloat16*>(sm);      // [2][8][32][24]
    uint32_t* hA32 = reinterpret_cast<uint32_t*>(sm);
    float* w0sm = reinterpret_cast<float*>(sm + HA_BYTES);          // [13][512]
    float (*xsm)[16] = reinterpret_cast<float(*)[16]>(sm + HA_BYTES + W0_BYTES);

    const int dir = blockIdx.y;
    const int b0  = blockIdx.x * BT;
    const int tid = threadIdx.x;
    const int lane = tid & 31, wn = tid >> 5;
    const uint4* frag = dir ? fragB : fragF;
    const float* bi = dir ? bihB : bihF;
    const float* bh = dir ? bhhB : bhhF;

    for (int i = tid; i < HA_BYTES / 4; i += 256) hA32[i] = 0u;

    int jcol[8];
#pragma unroll
    for (int i = 0; i < 8; ++i)
        jcol[i] = ((i >> 1) * 128) + (wn * 2 + (i & 1)) * 8 + (lane & 3) * 2;

    float biasv[8][2];
    if (is_layer0) {
        for (int i = tid; i < INP * GATES; i += 256)
            w0sm[i] = w0T[(size_t)dir * INP * GATES + i];
        int t0 = dir ? SEQ - 1 : 0;
        for (int i = tid; i < BT * INP; i += 256) {
            int b = i / INP, q = i % INP;
            xsm[b][q] = x[((size_t)(b0 + b) * SEQ + t0) * INP + q];
        }
#pragma unroll
        for (int i = 0; i < 8; ++i) {
            biasv[i][0] = bi[jcol[i]] + bh[jcol[i]];
            biasv[i][1] = bi[jcol[i] + 1] + bh[jcol[i] + 1];
        }
    }

    float c2[16];
#pragma unroll
    for (int i = 0; i < 16; ++i) c2[i] = 0.f;
    __syncthreads();

    const size_t xpdir = (size_t)dir * MROWS * GATES;
    const int rowsel = (lane & 7) + ((lane >> 3) & 1) * 8;
    const int lkb = (lane & 16) ? 8 : 0;

    for (int s = 0; s < SEQ; ++s) {
        const int t = dir ? (SEQ - 1 - s) : s;
        float acc[2][8][4];

        if (is_layer0) {
#pragma unroll
            for (int mt = 0; mt < 2; ++mt)
#pragma unroll
                for (int i = 0; i < 8; ++i) {
                    acc[mt][i][0] = biasv[i][0]; acc[mt][i][1] = biasv[i][1];
                    acc[mt][i][2] = biasv[i][0]; acc[mt][i][3] = biasv[i][1];
                }
            for (int q = 0; q < INP; ++q) {
                float2 w[8];
#pragma unroll
                for (int i = 0; i < 8; ++i)
                    w[i] = *reinterpret_cast<const float2*>(&w0sm[q * GATES + jcol[i]]);
#pragma unroll
                for (int mt = 0; mt < 2; ++mt)
#pragma unroll
                    for (int r8 = 0; r8 < 2; ++r8) {
                        float xv = xsm[mt * 16 + r8 * 8 + (lane >> 2)][q];
#pragma unroll
                        for (int i = 0; i < 8; ++i) {
                            acc[mt][i][r8 * 2]     += xv * w[i].x;
                            acc[mt][i][r8 * 2 + 1] += xv * w[i].y;
                        }
                    }
            }
        } else {
#pragma unroll
            for (int mt = 0; mt < 2; ++mt)
#pragma unroll
                for (int r8 = 0; r8 < 2; ++r8) {
                    int m = b0 + mt * 16 + r8 * 8 + (lane >> 2);
                    const float* xr = xp + xpdir + ((size_t)m * SEQ + t) * GATES;
#pragma unroll
                    for (int i = 0; i < 8; ++i) {
                        float2 v = *reinterpret_cast<const float2*>(&xr[jcol[i]]);
                        acc[mt][i][r8 * 2] = v.x; acc[mt][i][r8 * 2 + 1] = v.y;
                    }
                }
        }

#pragma unroll 1
        for (int kc = 0; kc < 8; ++kc) {
            uint4 bf[8];
#pragma unroll
            for (int i = 0; i < 8; ++i)
                bf[i] = frag[(((kc * 8 + wn) * 8) + i) * 32 + lane];
#pragma unroll
            for (int mt = 0; mt < 2; ++mt) {
                uint32_t ah[4], al[4];
                ldmx4(ah, &hA[((0 * 8 + kc) * 32 + mt * 16 + rowsel) * 24 + lkb]);
                ldmx4(al, &hA[((1 * 8 + kc) * 32 + mt * 16 + rowsel) * 24 + lkb]);
#pragma unroll
                for (int i = 0; i < 8; ++i) mma16816(acc[mt][i], ah, bf[i].x, bf[i].y);
#pragma unroll
                for (int i = 0; i < 8; ++i) mma16816(acc[mt][i], ah, bf[i].z, bf[i].w);
#pragma unroll
                for (int i = 0; i < 8; ++i) mma16816(acc[mt][i], al, bf[i].x, bf[i].y);
            }
        }
        __syncthreads();   // all ldmatrix reads of hA done

#pragma unroll
        for (int mt = 0; mt < 2; ++mt)
#pragma unroll
            for (int r8 = 0; r8 < 2; ++r8)
#pragma unroll
                for (int blk = 0; blk < 2; ++blk) {
                    int c0i = r8 * 2;
                    float ii0 = acc[mt][blk][c0i],     ii1 = acc[mt][blk][c0i + 1];
                    float ff0 = acc[mt][2 + blk][c0i], ff1 = acc[mt][2 + blk][c0i + 1];
                    float gg0 = acc[mt][4 + blk][c0i], gg1 = acc[mt][4 + blk][c0i + 1];
                    float oo0 = acc[mt][6 + blk][c0i], oo1 = acc[mt][6 + blk][c0i + 1];
                    int ci = ((mt * 2 + r8) * 2 + blk) * 2;
                    float cc0 = c2[ci], cc1 = c2[ci + 1];
                    cc0 = sigf(ff0) * cc0 + sigf(ii0) * tanhf_(gg0);
                    cc1 = sigf(ff1) * cc1 + sigf(ii1) * tanhf_(gg1);
                    float h0 = sigf(oo0) * tanhf_(cc0);
                    float h1 = sigf(oo1) * tanhf_(cc1);
                    c2[ci] = cc0; c2[ci + 1] = cc1;
                    int row = mt * 16 + r8 * 8 + (lane >> 2);
                    int hc0 = wn * 16 + blk * 8 + (lane & 3) * 2;
                    *reinterpret_cast<float2*>(
                        &y[((size_t)(b0 + row) * SEQ + t) * 256 + dir * 128 + hc0]) =
                        make_float2(h0, h1);
                    float h0h, h0l, h1h, h1l;
                    split_hl(h0, h0h, h0l); split_hl(h1, h1h, h1l);
                    int base = row * 12 + blk * 4 + (lane & 3);
                    hA32[((0 * 8 + wn) * 32) * 12 + base] = pack_bf2(h0h, h1h);
                    hA32[((1 * 8 + wn) * 32) * 12 + base] = pack_bf2(h0l, h1l);
                }
        if (is_layer0 && s < SEQ - 1) {
            int tn = dir ? (SEQ - 2 - s) : (s + 1);
            for (int i = tid; i < BT * INP; i += 256) {
                int b = i / INP, q = i % INP;
                xsm[b][q] = x[((size_t)(b0 + b) * SEQ + tn) * INP + q];
            }
        }
        __syncthreads();
    }
}

__global__ void final_kernel(const float* __restrict__ y, const float* __restrict__ wout,
                             const float* __restrict__ bout, float* __restrict__ out)
{
    const int b = blockIdx.x;
    const int tid = threadIdx.x;
    const float* yr = y + (size_t)b * 15360;
    float s0 = 0.f, s1 = 0.f;
    for (int j = tid * 4; j < 15360; j += 128 * 4) {
        float4 v = *reinterpret_cast<const float4*>(&yr[j]);
        v.x = fmaxf(v.x, 0.f); v.y = fmaxf(v.y, 0.f);
        v.z = fmaxf(v.z, 0.f); v.w = fmaxf(v.w, 0.f);
        float4 w0 = __ldg(reinterpret_cast<const float4*>(&wout[j]));
        float4 w1 = __ldg(reinterpret_cast<const float4*>(&wout[15360 + j]));
        s0 += v.x * w0.x + v.y * w0.y + v.z * w0.z + v.w * w0.w;
        s1 += v.x * w1.x + v.y * w1.y + v.z * w1.z + v.w * w1.w;
    }
#pragma unroll
    for (int off = 16; off > 0; off >>= 1) {
        s0 += __shfl_down_sync(0xffffffffu, s0, off);
        s1 += __shfl_down_sync(0xffffffffu, s1, off);
    }
    __shared__ float r0[4], r1[4];
    int wid = tid >> 5;
    if ((tid & 31) == 0) { r0[wid] = s0; r1[wid] = s1; }
    __syncthreads();
    if (tid == 0) {
        out[(size_t)b * 2 + 0] = r0[0] + r0[1] + r0[2] + r0[3] + __ldg(&bout[0]);
        out[(size_t)b * 2 + 1] = r1[0] + r1[1] + r1[2] + r1[3] + __ldg(&bout[1]);
    }
}

extern "C" void kernel_launch(void* const* d_in, const int* in_sizes, int n_in,
                              void* d_out, int out_size) {
    const float* x = (const float*)d_in[0];
    WPtrs P;
    for (int i = 0; i < 6; i++) {
        P.w_ih[i] = (const float*)d_in[1 + 4 * i];
        P.w_hh[i] = (const float*)d_in[2 + 4 * i];
        P.b_ih[i] = (const float*)d_in[3 + 4 * i];
        P.b_hh[i] = (const float*)d_in[4 + 4 * i];
    }
    const float* w_out = (const float*)d_in[25];
    const float* b_out = (const float*)d_in[26];
    float* out = (float*)d_out;

    float *xp, *y0, *y1, *w0T; uint4 *bfrag, *wfrag, *afrag;
    cudaGetSymbolAddress((void**)&xp,    g_xp);
    cudaGetSymbolAddress((void**)&y0,    g_y0);
    cudaGetSymbolAddress((void**)&y1,    g_y1);
    cudaGetSymbolAddress((void**)&w0T,   g_w0T);
    cudaGetSymbolAddress((void**)&bfrag, g_bfrag);
    cudaGetSymbolAddress((void**)&wfrag, g_wfrag);
    cudaGetSymbolAddress((void**)&afrag, g_afrag);

    cudaFuncSetAttribute(lstm_rec_mma,
                         cudaFuncAttributeMaxDynamicSharedMemorySize, SMEM_REC);

    prep_w0T<<<(2 * INP * GATES + 255) / 256, 256>>>(P, w0T);          // 0
    prep_bfrag<<<(BF_TOTAL + 255) / 256, 256>>>(P, bfrag);             // 1
    prep_wfrag<<<(WF_TOTAL + 255) / 256, 256>>>(P, wfrag);             // 2

    dim3 rgrid(BATCH / BT, 2);          // (128, 2)
    dim3 ggrid(MROWS / 128, GATES / 128, 2);
    int afblocks = (int)((AF_TOTAL / 2 + 255) / 256);

    lstm_rec_mma<<<rgrid, 256, SMEM_REC>>>(nullptr, x, w0T,            // 3
                                    P.b_ih[0], P.b_hh[0], P.b_ih[1], P.b_hh[1],
                                    wfrag + 0 * (size_t)WF_PER_W, wfrag + 1 * (size_t)WF_PER_W,
                                    y0, 1);
    prep_afrag<<<afblocks, 256>>>(y0, afrag);                          // 4
    gemm_mma2<<<ggrid, 256>>>(afrag, bfrag,                            // 5 (ncu -s 5)
                              P.b_ih[2], P.b_hh[2], P.b_ih[3], P.b_hh[3], xp);
    lstm_rec_mma<<<rgrid, 256, SMEM_REC>>>(xp, nullptr, w0T,           // 6
                                    P.b_ih[2], P.b_hh[2], P.b_ih[3], P.b_hh[3],
                                    wfrag + 2 * (size_t)WF_PER_W, wfrag + 3 * (size_t)WF_PER_W,
                                    y1, 0);
    prep_afrag<<<afblocks, 256>>>(y1, afrag);                          // 7
    gemm_mma2<<<ggrid, 256>>>(afrag, bfrag + BF_PER_LAYER,             // 8
                              P.b_ih[4], P.b_hh[4], P.b_ih[5], P.b_hh[5], xp);
    lstm_rec_mma<<<rgrid, 256, SMEM_REC>>>(xp, nullptr, w0T,           // 9
                                    P.b_ih[4], P.b_hh[4], P.b_ih[5], P.b_hh[5],
                                    wfrag + 4 * (size_t)WF_PER_W, wfrag + 5 * (size_t)WF_PER_W,
                                    y0, 0);
    final_kernel<<<BATCH, 128>>>(y0, w_out, b_out, out);               // 10
}

// round 11
// speedup vs baseline: 2.3941x; 1.1820x over previous
#include <cuda_runtime.h>
#include <cuda_bf16.h>
#include <cstdint>
#include <cstddef>

#define BATCH 4096
#define SEQ   60
#define INP   13
#define HID   128
#define GATES 512
#define MROWS (BATCH*SEQ)
#define BT    32

#define BF_PER_LAYER (2*16*64*32)      // gemm b-frag table (uint4), per layer
#define BF_TOTAL     (2*BF_PER_LAYER)
#define WF_PER_W     (8*8*8*32)        // whh frag per (layer,dir)
#define WF_TOTAL     (6*WF_PER_W)
#define AF_TOTAL     ((size_t)(MROWS/16) * 16 * 32 * 2)   // uint4 count

// rec smem
#define HA_BYTES   24576
#define W0_BYTES   26624
#define XS_BYTES   2048
#define SMEM_REC   (HA_BYTES + W0_BYTES + XS_BYTES)
// gemm smem: bfrag slice [16 kc][16 n8][32 lane] uint4
#define SMEM_GEMM  (16*16*32*16)
#define GX         16
#define TILES_PER_CTA (MROWS/128/GX)   // 120

__device__ float g_xp[(size_t)2 * MROWS * GATES];
__device__ float g_y0[(size_t)MROWS * 256];
__device__ float g_w0T[2 * INP * GATES];
__device__ uint4 g_bfrag[BF_TOTAL];
__device__ uint4 g_wfrag[WF_TOTAL];
__device__ uint4 g_afrag[AF_TOTAL];

__device__ __forceinline__ float sigf(float x) { return __fdividef(1.f, 1.f + __expf(-x)); }
__device__ __forceinline__ float tanhf_(float x) {
    float ax = fabsf(x); float e = __expf(-2.f * ax);
    return copysignf(__fdividef(1.f - e, 1.f + e), x);
}
__device__ __forceinline__ uint32_t pack_bf2(float a, float b) {
    __nv_bfloat162 t = __floats2bfloat162_rn(a, b);
    return *reinterpret_cast<uint32_t*>(&t);
}
__device__ __forceinline__ void split_hl(float v, float& hi, float& lo) {
    __nv_bfloat16 h = __float2bfloat16_rn(v);
    hi = __bfloat162float(h);
    lo = v - hi;
}
__device__ __forceinline__ void mma16816(float c[4], const uint32_t a[4],
                                         uint32_t b0, uint32_t b1) {
    asm volatile("mma.sync.aligned.m16n8k16.row.col.f32.bf16.bf16.f32 "
                 "{%0,%1,%2,%3}, {%4,%5,%6,%7}, {%8,%9}, {%0,%1,%2,%3};"
                 : "+f"(c[0]), "+f"(c[1]), "+f"(c[2]), "+f"(c[3])
                 : "r"(a[0]), "r"(a[1]), "r"(a[2]), "r"(a[3]), "r"(b0), "r"(b1));
}
__device__ __forceinline__ void mma16816u(float c[4], const uint4& a,
                                          uint32_t b0, uint32_t b1) {
    asm volatile("mma.sync.aligned.m16n8k16.row.col.f32.bf16.bf16.f32 "
                 "{%0,%1,%2,%3}, {%4,%5,%6,%7}, {%8,%9}, {%0,%1,%2,%3};"
                 : "+f"(c[0]), "+f"(c[1]), "+f"(c[2]), "+f"(c[3])
                 : "r"(a.x), "r"(a.y), "r"(a.z), "r"(a.w), "r"(b0), "r"(b1));
}
__device__ __forceinline__ void ldmx4(uint32_t r[4], const void* p) {
    uint32_t addr = (uint32_t)__cvta_generic_to_shared(p);
    asm volatile("ldmatrix.sync.aligned.m8n8.x4.shared.b16 {%0,%1,%2,%3}, [%4];"
                 : "=r"(r[0]), "=r"(r[1]), "=r"(r[2]), "=r"(r[3]) : "r"(addr));
}

struct WPtrs {
    const float* w_ih[6];
    const float* w_hh[6];
    const float* b_ih[6];
    const float* b_hh[6];
};

__global__ void prep_w0T(WPtrs P, float* __restrict__ dst) {
    int idx = blockIdx.x * 256 + threadIdx.x;
    if (idx >= 2 * INP * GATES) return;
    int d = idx / (INP * GATES), rem = idx % (INP * GATES);
    int q = rem / GATES, j = rem % GATES;
    dst[idx] = P.w_ih[d][j * INP + q];
}

__global__ void prep_bfrag(WPtrs P, uint4* __restrict__ bf) {
    int idx = blockIdx.x * 256 + threadIdx.x;
    if (idx >= BF_TOTAL) return;
    int lane = idx & 31;
    int n8   = (idx >> 5) & 63;
    int kc   = (idx >> 11) & 15;
    int dir  = (idx >> 15) & 1;
    int layer = idx >> 16;
    const float* W = P.w_ih[2 + layer * 2 + dir];
    int n = n8 * 8 + (lane >> 2);
    int kb = kc * 16 + (lane & 3) * 2;
    float v00 = W[n * 256 + kb + 0], v01 = W[n * 256 + kb + 1];
    float v10 = W[n * 256 + kb + 8], v11 = W[n * 256 + kb + 9];
    float h00, l00, h01, l01, h10, l10, h11, l11;
    split_hl(v00, h00, l00); split_hl(v01, h01, l01);
    split_hl(v10, h10, l10); split_hl(v11, h11, l11);
    uint4 o;
    o.x = pack_bf2(h00, h01); o.y = pack_bf2(h10, h11);
    o.z = pack_bf2(l00, l01); o.w = pack_bf2(l10, l11);
    bf[idx] = o;
}

__global__ void prep_wfrag(WPtrs P, uint4* __restrict__ wf) {
    int idx = blockIdx.x * 256 + threadIdx.x;
    if (idx >= WF_TOTAL) return;
    int lane = idx & 31;
    int i    = (idx >> 5) & 7;
    int wn   = (idx >> 8) & 7;
    int kc   = (idx >> 11) & 7;
    int w    = idx >> 14;
    int g = i >> 1, blk = i & 1;
    int n = (g * 16 + wn * 2 + blk) * 8 + (lane >> 2);
    int kb = kc * 16 + (lane & 3) * 2;
    const float* W = P.w_hh[w];
    float v00 = W[n * HID + kb + 0], v01 = W[n * HID + kb + 1];
    float v10 = W[n * HID + kb + 8], v11 = W[n * HID + kb + 9];
    float h00, l00, h01, l01, h10, l10, h11, l11;
    split_hl(v00, h00, l00); split_hl(v01, h01, l01);
    split_hl(v10, h10, l10); split_hl(v11, h11, l11);
    uint4 o;
    o.x = pack_bf2(h00, h01); o.y = pack_bf2(h10, h11);
    o.z = pack_bf2(l00, l01); o.w = pack_bf2(l10, l11);
    wf[idx] = o;
}
__global__ void dummy_kernel() {}

// ---- persistent-tile GEMM: bfrag slice in smem, loop over m-tiles ----
__global__ __launch_bounds__(512, 1)
void gemm_smem(const uint4* __restrict__ afrag,
               const uint4* __restrict__ bfrag,
               const float* __restrict__ bihF, const float* __restrict__ bhhF,
               const float* __restrict__ bihB, const float* __restrict__ bhhB,
               float* __restrict__ xp)
{
    extern __shared__ __align__(16) uint4 bs[];   // [16 kc][16 n8][32 lane]
    const int dir = blockIdx.z;
    const int ny  = blockIdx.y;                   // n-tile of 128
    const int tid = threadIdx.x;
    const int lane = tid & 31, wid = tid >> 5;
    const int wm = wid & 3, wn = wid >> 2;        // 4m x 4n
    const float* bih = dir ? bihB : bihF;
    const float* bhh = dir ? bhhB : bhhF;

    // load bfrag slice once (8192 uint4)
    for (int i = tid; i < 16 * 16 * 32; i += 512) {
        int kc = i >> 9, rem = i & 511;
        bs[i] = bfrag[((size_t)(dir * 16 + kc) * 64 + ny * 16) * 32 + rem];
    }
    __syncthreads();

    // biases for this warp's 4 n8-groups
    const int t2 = (lane & 3) * 2;
    float bb0[4], bb1[4];
#pragma unroll
    for (int j = 0; j < 4; ++j) {
        int n = (ny * 16 + wn * 4 + j) * 8 + t2;
        bb0[j] = bih[n] + bhh[n];
        bb1[j] = bih[n + 1] + bhh[n + 1];
    }

    const int g = lane >> 2;
    const size_t tile0 = (size_t)blockIdx.x * TILES_PER_CTA;

    for (int it = 0; it < TILES_PER_CTA; ++it) {
        const size_t tile = tile0 + it;
        float acc[2][4][4];
#pragma unroll
        for (int a = 0; a < 2; a++)
#pragma unroll
            for (int b = 0; b < 4; b++)
#pragma unroll
                for (int c = 0; c < 4; c++) acc[a][b][c] = 0.f;

#pragma unroll 4
        for (int kc = 0; kc < 16; ++kc) {
            uint4 ah[2], al[2];
#pragma unroll
            for (int ms = 0; ms < 2; ++ms) {
                size_t base = (((tile * 8 + wm * 2 + ms) * 16 + kc) * 32 + lane) * 2;
                ah[ms] = afrag[base];
                al[ms] = afrag[base + 1];
            }
            uint4 bf[4];
#pragma unroll
            for (int j = 0; j < 4; ++j)
                bf[j] = bs[(kc * 16 + wn * 4 + j) * 32 + lane];
#pragma unroll
            for (int j = 0; j < 4; ++j)
#pragma unroll
                for (int ms = 0; ms < 2; ++ms) {
                    mma16816u(acc[ms][j], ah[ms], bf[j].x, bf[j].y);
                    mma16816u(acc[ms][j], ah[ms], bf[j].z, bf[j].w);
                    mma16816u(acc[ms][j], al[ms], bf[j].x, bf[j].y);
                }
        }

        const size_t m0 = tile * 128;
#pragma unroll
        for (int ms = 0; ms < 2; ++ms) {
#pragma unroll
            for (int j = 0; j < 4; ++j) {
                int n = (ny * 16 + wn * 4 + j) * 8 + t2;
                size_t r0 = (size_t)dir * MROWS + m0 + (wm * 2 + ms) * 16 + g;
                *reinterpret_cast<float2*>(&xp[r0 * 512 + n]) =
                    make_float2(acc[ms][j][0] + bb0[j], acc[ms][j][1] + bb1[j]);
                *reinterpret_cast<float2*>(&xp[(r0 + 8) * 512 + n]) =
                    make_float2(acc[ms][j][2] + bb0[j], acc[ms][j][3] + bb1[j]);
            }
        }
    }
}

// ---- tensor-core recurrence: BT=32, 2 CTAs/SM; writes afrag OR y ----
__global__ __launch_bounds__(256, 2)
void lstm_rec_mma(const float* __restrict__ xp, const float* __restrict__ x,
                  const float* __restrict__ w0T,
                  const float* __restrict__ bihF, const float* __restrict__ bhhF,
                  const float* __restrict__ bihB, const float* __restrict__ bhhB,
                  const uint4* __restrict__ fragF, const uint4* __restrict__ fragB,
                  float* __restrict__ y, uint4* __restrict__ af_out, int is_layer0)
{
    extern __shared__ __align__(16) char sm[];
    __nv_bfloat16* hA = reinterpret_cast<__nv_bfloat16*>(sm);      // [2][8][32][24]
    uint32_t* hA32 = reinterpret_cast<uint32_t*>(sm);
    float* w0sm = reinterpret_cast<float*>(sm + HA_BYTES);          // [13][512]
    float (*xsm)[16] = reinterpret_cast<float(*)[16]>(sm + HA_BYTES + W0_BYTES);

    const int dir = blockIdx.y;
    const int b0  = blockIdx.x * BT;
    const int tid = threadIdx.x;
    const int lane = tid & 31, wn = tid >> 5;
    const uint4* frag = dir ? fragB : fragF;
    const float* bi = dir ? bihB : bihF;
    const float* bh = dir ? bhhB : bhhF;

    for (int i = tid; i < HA_BYTES / 4; i += 256) hA32[i] = 0u;

    int jcol[8];
#pragma unroll
    for (int i = 0; i < 8; ++i)
        jcol[i] = ((i >> 1) * 128) + (wn * 2 + (i & 1)) * 8 + (lane & 3) * 2;

    float biasv[8][2];
    if (is_layer0) {
        for (int i = tid; i < INP * GATES; i += 256)
            w0sm[i] = w0T[(size_t)dir * INP * GATES + i];
        int t0 = dir ? SEQ - 1 : 0;
        for (int i = tid; i < BT * INP; i += 256) {
            int b = i / INP, q = i % INP;
            xsm[b][q] = x[((size_t)(b0 + b) * SEQ + t0) * INP + q];
        }
#pragma unroll
        for (int i = 0; i < 8; ++i) {
            biasv[i][0] = bi[jcol[i]] + bh[jcol[i]];
            biasv[i][1] = bi[jcol[i] + 1] + bh[jcol[i] + 1];
        }
    }

    float c2[16];
#pragma unroll
    for (int i = 0; i < 16; ++i) c2[i] = 0.f;
    __syncthreads();

    const size_t xpdir = (size_t)dir * MROWS * GATES;
    const int rowsel = (lane & 7) + ((lane >> 3) & 1) * 8;
    const int lkb = (lane & 16) ? 8 : 0;

    for (int s = 0; s < SEQ; ++s) {
        const int t = dir ? (SEQ - 1 - s) : s;
        float acc[2][8][4];

        if (is_layer0) {
#pragma unroll
            for (int mt = 0; mt < 2; ++mt)
#pragma unroll
                for (int i = 0; i < 8; ++i) {
                    acc[mt][i][0] = biasv[i][0]; acc[mt][i][1] = biasv[i][1];
                    acc[mt][i][2] = biasv[i][0]; acc[mt][i][3] = biasv[i][1];
                }
            for (int q = 0; q < INP; ++q) {
                float2 w[8];
#pragma unroll
                for (int i = 0; i < 8; ++i)
                    w[i] = *reinterpret_cast<const float2*>(&w0sm[q * GATES + jcol[i]]);
#pragma unroll
                for (int mt = 0; mt < 2; ++mt)
#pragma unroll
                    for (int r8 = 0; r8 < 2; ++r8) {
                        float xv = xsm[mt * 16 + r8 * 8 + (lane >> 2)][q];
#pragma unroll
                        for (int i = 0; i < 8; ++i) {
                            acc[mt][i][r8 * 2]     += xv * w[i].x;
                            acc[mt][i][r8 * 2 + 1] += xv * w[i].y;
                        }
                    }
            }
        } else {
#pragma unroll
            for (int mt = 0; mt < 2; ++mt)
#pragma unroll
                for (int r8 = 0; r8 < 2; ++r8) {
                    int m = b0 + mt * 16 + r8 * 8 + (lane >> 2);
                    const float* xr = xp + xpdir + ((size_t)m * SEQ + t) * GATES;
#pragma unroll
                    for (int i = 0; i < 8; ++i) {
                        float2 v = *reinterpret_cast<const float2*>(&xr[jcol[i]]);
                        acc[mt][i][r8 * 2] = v.x; acc[mt][i][r8 * 2 + 1] = v.y;
                    }
                }
        }

#pragma unroll 1
        for (int kc = 0; kc < 8; ++kc) {
            uint4 bf[8];
#pragma unroll
            for (int i = 0; i < 8; ++i)
                bf[i] = frag[(((kc * 8 + wn) * 8) + i) * 32 + lane];
#pragma unroll
            for (int mt = 0; mt < 2; ++mt) {
                uint32_t ah[4], al[4];
                ldmx4(ah, &hA[((0 * 8 + kc) * 32 + mt * 16 + rowsel) * 24 + lkb]);
                ldmx4(al, &hA[((1 * 8 + kc) * 32 + mt * 16 + rowsel) * 24 + lkb]);
#pragma unroll
                for (int i = 0; i < 8; ++i) mma16816(acc[mt][i], ah, bf[i].x, bf[i].y);
#pragma unroll
                for (int i = 0; i < 8; ++i) mma16816(acc[mt][i], ah, bf[i].z, bf[i].w);
#pragma unroll
                for (int i = 0; i < 8; ++i) mma16816(acc[mt][i], al, bf[i].x, bf[i].y);
            }
        }
        __syncthreads();   // all ldmatrix reads of hA done

#pragma unroll
        for (int mt = 0; mt < 2; ++mt)
#pragma unroll
            for (int r8 = 0; r8 < 2; ++r8)
#pragma unroll
                for (int blk = 0; blk < 2; ++blk) {
                    int c0i = r8 * 2;
                    float ii0 = acc[mt][blk][c0i],     ii1 = acc[mt][blk][c0i + 1];
                    float ff0 = acc[mt][2 + blk][c0i], ff1 = acc[mt][2 + blk][c0i + 1];
                    float gg0 = acc[mt][4 + blk][c0i], gg1 = acc[mt][4 + blk][c0i + 1];
                    float oo0 = acc[mt][6 + blk][c0i], oo1 = acc[mt][6 + blk][c0i + 1];
                    int ci = ((mt * 2 + r8) * 2 + blk) * 2;
                    float cc0 = c2[ci], cc1 = c2[ci + 1];
                    cc0 = sigf(ff0) * cc0 + sigf(ii0) * tanhf_(gg0);
                    cc1 = sigf(ff1) * cc1 + sigf(ii1) * tanhf_(gg1);
                    float h0 = sigf(oo0) * tanhf_(cc0);
                    float h1 = sigf(oo1) * tanhf_(cc1);
                    c2[ci] = cc0; c2[ci + 1] = cc1;
                    int row = mt * 16 + r8 * 8 + (lane >> 2);
                    float h0h, h0l, h1h, h1l;
                    split_hl(h0, h0h, h0l); split_hl(h1, h1h, h1l);
                    if (af_out) {
                        // write next-layer A fragments directly
                        int m = (b0 + row) * SEQ + t;
                        int mtg = m >> 4, r = m & 15;
                        int kcg = dir * 8 + wn;
                        int lane_f = ((r & 7) << 2) | (lane & 3);
                        int comp = (blk << 1) | (r >> 3);
                        uint32_t* basep = reinterpret_cast<uint32_t*>(
                            af_out + ((size_t)(mtg * 16 + kcg) * 32 + lane_f) * 2);
                        basep[comp]     = pack_bf2(h0h, h1h);
                        basep[4 + comp] = pack_bf2(h0l, h1l);
                    } else {
                        int hc0 = wn * 16 + blk * 8 + (lane & 3) * 2;
                        *reinterpret_cast<float2*>(
                            &y[((size_t)(b0 + row) * SEQ + t) * 256 + dir * 128 + hc0]) =
                            make_float2(h0, h1);
                    }
                    int base = row * 12 + blk * 4 + (lane & 3);
                    hA32[((0 * 8 + wn) * 32) * 12 + base] = pack_bf2(h0h, h1h);
                    hA32[((1 * 8 + wn) * 32) * 12 + base] = pack_bf2(h0l, h1l);
                }
        if (is_layer0 && s < SEQ - 1) {
            int tn = dir ? (SEQ - 2 - s) : (s + 1);
            for (int i = tid; i < BT * INP; i += 256) {
                int b = i / INP, q = i % INP;
                xsm[b][q] = x[((size_t)(b0 + b) * SEQ + tn) * INP + q];
            }
        }
        __syncthreads();
    }
}

__global__ void final_kernel(const float* __restrict__ y, const float* __restrict__ wout,
                             const float* __restrict__ bout, float* __restrict__ out)
{
    const int b = blockIdx.x;
    const int tid = threadIdx.x;
    const float* yr = y + (size_t)b * 15360;
    float s0 = 0.f, s1 = 0.f;
    for (int j = tid * 4; j < 15360; j += 128 * 4) {
        float4 v = *reinterpret_cast<const float4*>(&yr[j]);
        v.x = fmaxf(v.x, 0.f); v.y = fmaxf(v.y, 0.f);
        v.z = fmaxf(v.z, 0.f); v.w = fmaxf(v.w, 0.f);
        float4 w0 = __ldg(reinterpret_cast<const float4*>(&wout[j]));
        float4 w1 = __ldg(reinterpret_cast<const float4*>(&wout[15360 + j]));
        s0 += v.x * w0.x + v.y * w0.y + v.z * w0.z + v.w * w0.w;
        s1 += v.x * w1.x + v.y * w1.y + v.z * w1.z + v.w * w1.w;
    }
#pragma unroll
    for (int off = 16; off > 0; off >>= 1) {
        s0 += __shfl_down_sync(0xffffffffu, s0, off);
        s1 += __shfl_down_sync(0xffffffffu, s1, off);
    }
    __shared__ float r0[4], r1[4];
    int wid = tid >> 5;
    if ((tid & 31) == 0) { r0[wid] = s0; r1[wid] = s1; }
    __syncthreads();
    if (tid == 0) {
        out[(size_t)b * 2 + 0] = r0[0] + r0[1] + r0[2] + r0[3] + __ldg(&bout[0]);
        out[(size_t)b * 2 + 1] = r1[0] + r1[1] + r1[2] + r1[3] + __ldg(&bout[1]);
    }
}

extern "C" void kernel_launch(void* const* d_in, const int* in_sizes, int n_in,
                              void* d_out, int out_size) {
    const float* x = (const float*)d_in[0];
    WPtrs P;
    for (int i = 0; i < 6; i++) {
        P.w_ih[i] = (const float*)d_in[1 + 4 * i];
        P.w_hh[i] = (const float*)d_in[2 + 4 * i];
        P.b_ih[i] = (const float*)d_in[3 + 4 * i];
        P.b_hh[i] = (const float*)d_in[4 + 4 * i];
    }
    const float* w_out = (const float*)d_in[25];
    const float* b_out = (const float*)d_in[26];
    float* out = (float*)d_out;

    float *xp, *y0, *w0T; uint4 *bfrag, *wfrag, *afrag;
    cudaGetSymbolAddress((void**)&xp,    g_xp);
    cudaGetSymbolAddress((void**)&y0,    g_y0);
    cudaGetSymbolAddress((void**)&w0T,   g_w0T);
    cudaGetSymbolAddress((void**)&bfrag, g_bfrag);
    cudaGetSymbolAddress((void**)&wfrag, g_wfrag);
    cudaGetSymbolAddress((void**)&afrag, g_afrag);

    cudaFuncSetAttribute(lstm_rec_mma,
                         cudaFuncAttributeMaxDynamicSharedMemorySize, SMEM_REC);
    cudaFuncSetAttribute(gemm_smem,
                         cudaFuncAttributeMaxDynamicSharedMemorySize, SMEM_GEMM);

    prep_w0T<<<(2 * INP * GATES + 255) / 256, 256>>>(P, w0T);          // 0
    prep_bfrag<<<(BF_TOTAL + 255) / 256, 256>>>(P, bfrag);             // 1
    prep_wfrag<<<(WF_TOTAL + 255) / 256, 256>>>(P, wfrag);             // 2

    dim3 rgrid(BATCH / BT, 2);          // (128, 2)
    dim3 ggrid(GX, 4, 2);               // (16, 4, 2) = 128 CTAs x 512 thr

    lstm_rec_mma<<<rgrid, 256, SMEM_REC>>>(nullptr, x, w0T,            // 3
                                    P.b_ih[0], P.b_hh[0], P.b_ih[1], P.b_hh[1],
                                    wfrag + 0 * (size_t)WF_PER_W, wfrag + 1 * (size_t)WF_PER_W,
                                    y0, afrag, 1);
    dummy_kernel<<<1, 32>>>();                                         // 4
    gemm_smem<<<ggrid, 512, SMEM_GEMM>>>(afrag, bfrag,                 // 5 (ncu -s 5)
                              P.b_ih[2], P.b_hh[2], P.b_ih[3], P.b_hh[3], xp);
    lstm_rec_mma<<<rgrid, 256, SMEM_REC>>>(xp, nullptr, w0T,           // 6
                                    P.b_ih[2], P.b_hh[2], P.b_ih[3], P.b_hh[3],
                                    wfrag + 2 * (size_t)WF_PER_W, wfrag + 3 * (size_t)WF_PER_W,
                                    y0, afrag, 0);
    gemm_smem<<<ggrid, 512, SMEM_GEMM>>>(afrag, bfrag + BF_PER_LAYER,  // 7
                              P.b_ih[4], P.b_hh[4], P.b_ih[5], P.b_hh[5], xp);
    lstm_rec_mma<<<rgrid, 256, SMEM_REC>>>(xp, nullptr, w0T,           // 8
                                    P.b_ih[4], P.b_hh[4], P.b_ih[5], P.b_hh[5],
                                    wfrag + 4 * (size_t)WF_PER_W, wfrag + 5 * (size_t)WF_PER_W,
                                    y0, nullptr, 0);
    final_kernel<<<BATCH, 128>>>(y0, w_out, b_out, out);               // 9
}

// round 12
// speedup vs baseline: 2.5747x; 1.0754x over previous
#include <cuda_runtime.h>
#include <cuda_bf16.h>
#include <cstdint>
#include <cstddef>

#define BATCH 4096
#define SEQ   60
#define INP   13
#define HID   128
#define GATES 512
#define MROWS (BATCH*SEQ)
#define BT    32

#define BF_PER_LAYER (2*16*64*32)      // gemm b-frag table (uint4), per layer
#define BF_TOTAL     (2*BF_PER_LAYER)
#define WF_PER_W     (8*8*8*32)        // whh frag per (layer,dir)
#define WF_TOTAL     (6*WF_PER_W)
#define AF_TOTAL     ((size_t)(MROWS/16) * 16 * 32 * 2)   // uint4 count

// rec smem: hA 2 buffers of [2][8][32][24] bf16, w0sm, xsm 2 buffers
#define HA_HALF    24576
#define HA_BYTES   (2*HA_HALF)
#define W0_BYTES   26624
#define XS_BYTES   (2*2048)
#define SMEM_REC   (HA_BYTES + W0_BYTES + XS_BYTES)
// gemm smem: bfrag slice [16 kc][16 n8][32 lane] uint4
#define SMEM_GEMM  (16*16*32*16)
#define GX         16
#define TILES_PER_CTA (MROWS/128/GX)   // 120

__device__ float g_xp[(size_t)2 * MROWS * GATES];
__device__ float g_y0[(size_t)MROWS * 256];
__device__ float g_w0T[2 * INP * GATES];
__device__ uint4 g_bfrag[BF_TOTAL];
__device__ uint4 g_wfrag[WF_TOTAL];
__device__ uint4 g_afrag[AF_TOTAL];

__device__ __forceinline__ float sigf(float x) { return __fdividef(1.f, 1.f + __expf(-x)); }
__device__ __forceinline__ float tanhf_(float x) {
    float ax = fabsf(x); float e = __expf(-2.f * ax);
    return copysignf(__fdividef(1.f - e, 1.f + e), x);
}
__device__ __forceinline__ uint32_t pack_bf2(float a, float b) {
    __nv_bfloat162 t = __floats2bfloat162_rn(a, b);
    return *reinterpret_cast<uint32_t*>(&t);
}
__device__ __forceinline__ void split_hl(float v, float& hi, float& lo) {
    __nv_bfloat16 h = __float2bfloat16_rn(v);
    hi = __bfloat162float(h);
    lo = v - hi;
}
__device__ __forceinline__ void mma16816(float c[4], const uint32_t a[4],
                                         uint32_t b0, uint32_t b1) {
    asm volatile("mma.sync.aligned.m16n8k16.row.col.f32.bf16.bf16.f32 "
                 "{%0,%1,%2,%3}, {%4,%5,%6,%7}, {%8,%9}, {%0,%1,%2,%3};"
                 : "+f"(c[0]), "+f"(c[1]), "+f"(c[2]), "+f"(c[3])
                 : "r"(a[0]), "r"(a[1]), "r"(a[2]), "r"(a[3]), "r"(b0), "r"(b1));
}
__device__ __forceinline__ void mma16816u(float c[4], const uint4& a,
                                          uint32_t b0, uint32_t b1) {
    asm volatile("mma.sync.aligned.m16n8k16.row.col.f32.bf16.bf16.f32 "
                 "{%0,%1,%2,%3}, {%4,%5,%6,%7}, {%8,%9}, {%0,%1,%2,%3};"
                 : "+f"(c[0]), "+f"(c[1]), "+f"(c[2]), "+f"(c[3])
                 : "r"(a.x), "r"(a.y), "r"(a.z), "r"(a.w), "r"(b0), "r"(b1));
}
__device__ __forceinline__ void ldmx4(uint32_t r[4], const void* p) {
    uint32_t addr = (uint32_t)__cvta_generic_to_shared(p);
    asm volatile("ldmatrix.sync.aligned.m8n8.x4.shared.b16 {%0,%1,%2,%3}, [%4];"
                 : "=r"(r[0]), "=r"(r[1]), "=r"(r[2]), "=r"(r[3]) : "r"(addr));
}

struct WPtrs {
    const float* w_ih[6];
    const float* w_hh[6];
    const float* b_ih[6];
    const float* b_hh[6];
};

__global__ void prep_w0T(WPtrs P, float* __restrict__ dst) {
    int idx = blockIdx.x * 256 + threadIdx.x;
    if (idx >= 2 * INP * GATES) return;
    int d = idx / (INP * GATES), rem = idx % (INP * GATES);
    int q = rem / GATES, j = rem % GATES;
    dst[idx] = P.w_ih[d][j * INP + q];
}

__global__ void prep_bfrag(WPtrs P, uint4* __restrict__ bf) {
    int idx = blockIdx.x * 256 + threadIdx.x;
    if (idx >= BF_TOTAL) return;
    int lane = idx & 31;
    int n8   = (idx >> 5) & 63;
    int kc   = (idx >> 11) & 15;
    int dir  = (idx >> 15) & 1;
    int layer = idx >> 16;
    const float* W = P.w_ih[2 + layer * 2 + dir];
    int n = n8 * 8 + (lane >> 2);
    int kb = kc * 16 + (lane & 3) * 2;
    float v00 = W[n * 256 + kb + 0], v01 = W[n * 256 + kb + 1];
    float v10 = W[n * 256 + kb + 8], v11 = W[n * 256 + kb + 9];
    float h00, l00, h01, l01, h10, l10, h11, l11;
    split_hl(v00, h00, l00); split_hl(v01, h01, l01);
    split_hl(v10, h10, l10); split_hl(v11, h11, l11);
    uint4 o;
    o.x = pack_bf2(h00, h01); o.y = pack_bf2(h10, h11);
    o.z = pack_bf2(l00, l01); o.w = pack_bf2(l10, l11);
    bf[idx] = o;
}

__global__ void prep_wfrag(WPtrs P, uint4* __restrict__ wf) {
    int idx = blockIdx.x * 256 + threadIdx.x;
    if (idx >= WF_TOTAL) return;
    int lane = idx & 31;
    int i    = (idx >> 5) & 7;
    int wn   = (idx >> 8) & 7;
    int kc   = (idx >> 11) & 7;
    int w    = idx >> 14;
    int g = i >> 1, blk = i & 1;
    int n = (g * 16 + wn * 2 + blk) * 8 + (lane >> 2);
    int kb = kc * 16 + (lane & 3) * 2;
    const float* W = P.w_hh[w];
    float v00 = W[n * HID + kb + 0], v01 = W[n * HID + kb + 1];
    float v10 = W[n * HID + kb + 8], v11 = W[n * HID + kb + 9];
    float h00, l00, h01, l01, h10, l10, h11, l11;
    split_hl(v00, h00, l00); split_hl(v01, h01, l01);
    split_hl(v10, h10, l10); split_hl(v11, h11, l11);
    uint4 o;
    o.x = pack_bf2(h00, h01); o.y = pack_bf2(h10, h11);
    o.z = pack_bf2(l00, l01); o.w = pack_bf2(l10, l11);
    wf[idx] = o;
}
__global__ void dummy_kernel() {}

// ---- persistent-tile GEMM: bfrag slice in smem, loop over m-tiles ----
// m-index is the PERMUTED m' = t*BATCH + b ordering (agnostic here).
__global__ __launch_bounds__(512, 1)
void gemm_smem(const uint4* __restrict__ afrag,
               const uint4* __restrict__ bfrag,
               const float* __restrict__ bihF, const float* __restrict__ bhhF,
               const float* __restrict__ bihB, const float* __restrict__ bhhB,
               float* __restrict__ xp)
{
    extern __shared__ __align__(16) uint4 bs[];   // [16 kc][16 n8][32 lane]
    const int dir = blockIdx.z;
    const int ny  = blockIdx.y;
    const int tid = threadIdx.x;
    const int lane = tid & 31, wid = tid >> 5;
    const int wm = wid & 3, wn = wid >> 2;
    const float* bih = dir ? bihB : bihF;
    const float* bhh = dir ? bhhB : bhhF;

    for (int i = tid; i < 16 * 16 * 32; i += 512) {
        int kc = i >> 9, rem = i & 511;
        bs[i] = bfrag[((size_t)(dir * 16 + kc) * 64 + ny * 16) * 32 + rem];
    }
    __syncthreads();

    const int t2 = (lane & 3) * 2;
    float bb0[4], bb1[4];
#pragma unroll
    for (int j = 0; j < 4; ++j) {
        int n = (ny * 16 + wn * 4 + j) * 8 + t2;
        bb0[j] = bih[n] + bhh[n];
        bb1[j] = bih[n + 1] + bhh[n + 1];
    }

    const int g = lane >> 2;
    const size_t tile0 = (size_t)blockIdx.x * TILES_PER_CTA;

    for (int it = 0; it < TILES_PER_CTA; ++it) {
        const size_t tile = tile0 + it;
        float acc[2][4][4];
#pragma unroll
        for (int a = 0; a < 2; a++)
#pragma unroll
            for (int b = 0; b < 4; b++)
#pragma unroll
                for (int c = 0; c < 4; c++) acc[a][b][c] = 0.f;

#pragma unroll 4
        for (int kc = 0; kc < 16; ++kc) {
            uint4 ah[2], al[2];
#pragma unroll
            for (int ms = 0; ms < 2; ++ms) {
                size_t base = (((tile * 8 + wm * 2 + ms) * 16 + kc) * 32 + lane) * 2;
                ah[ms] = afrag[base];
                al[ms] = afrag[base + 1];
            }
            uint4 bf[4];
#pragma unroll
            for (int j = 0; j < 4; ++j)
                bf[j] = bs[(kc * 16 + wn * 4 + j) * 32 + lane];
#pragma unroll
            for (int j = 0; j < 4; ++j)
#pragma unroll
                for (int ms = 0; ms < 2; ++ms) {
                    mma16816u(acc[ms][j], ah[ms], bf[j].x, bf[j].y);
                    mma16816u(acc[ms][j], ah[ms], bf[j].z, bf[j].w);
                    mma16816u(acc[ms][j], al[ms], bf[j].x, bf[j].y);
                }
        }

        const size_t m0 = tile * 128;
#pragma unroll
        for (int ms = 0; ms < 2; ++ms) {
#pragma unroll
            for (int j = 0; j < 4; ++j) {
                int n = (ny * 16 + wn * 4 + j) * 8 + t2;
                size_t r0 = (size_t)dir * MROWS + m0 + (wm * 2 + ms) * 16 + g;
                *reinterpret_cast<float2*>(&xp[r0 * 512 + n]) =
                    make_float2(acc[ms][j][0] + bb0[j], acc[ms][j][1] + bb1[j]);
                *reinterpret_cast<float2*>(&xp[(r0 + 8) * 512 + n]) =
                    make_float2(acc[ms][j][2] + bb0[j], acc[ms][j][3] + bb1[j]);
            }
        }
    }
}

// ---- tensor-core recurrence: double-buffered hA, single sync/step,
//      coalesced afrag output (m' = t*BATCH + b ordering) ----
__global__ __launch_bounds__(256, 2)
void lstm_rec_mma(const float* __restrict__ xp, const float* __restrict__ x,
                  const float* __restrict__ w0T,
                  const float* __restrict__ bihF, const float* __restrict__ bhhF,
                  const float* __restrict__ bihB, const float* __restrict__ bhhB,
                  const uint4* __restrict__ fragF, const uint4* __restrict__ fragB,
                  float* __restrict__ y, uint4* __restrict__ af_out, int is_layer0)
{
    extern __shared__ __align__(16) char sm[];
    __nv_bfloat16* hA = reinterpret_cast<__nv_bfloat16*>(sm);      // 2 x [2][8][32][24]
    uint32_t* hA32 = reinterpret_cast<uint32_t*>(sm);
    float* w0sm = reinterpret_cast<float*>(sm + HA_BYTES);          // [13][512]
    float (*xsm)[BT][16] = reinterpret_cast<float(*)[BT][16]>(sm + HA_BYTES + W0_BYTES);

    const int dir = blockIdx.y;
    const int b0  = blockIdx.x * BT;
    const int tid = threadIdx.x;
    const int lane = tid & 31, wn = tid >> 5;
    const uint4* frag = dir ? fragB : fragF;
    const float* bi = dir ? bihB : bihF;
    const float* bh = dir ? bhhB : bhhF;

    // zero read-buffer 0 (h = 0 at s=0)
    for (int i = tid; i < HA_HALF / 4; i += 256) hA32[i] = 0u;

    int jcol[8];
#pragma unroll
    for (int i = 0; i < 8; ++i)
        jcol[i] = ((i >> 1) * 128) + (wn * 2 + (i & 1)) * 8 + (lane & 3) * 2;

    float biasv[8][2];
    if (is_layer0) {
        for (int i = tid; i < INP * GATES; i += 256)
            w0sm[i] = w0T[(size_t)dir * INP * GATES + i];
        int t0 = dir ? SEQ - 1 : 0;
        for (int i = tid; i < BT * INP; i += 256) {
            int b = i / INP, q = i % INP;
            xsm[0][b][q] = x[((size_t)(b0 + b) * SEQ + t0) * INP + q];
        }
#pragma unroll
        for (int i = 0; i < 8; ++i) {
            biasv[i][0] = bi[jcol[i]] + bh[jcol[i]];
            biasv[i][1] = bi[jcol[i] + 1] + bh[jcol[i] + 1];
        }
    }

    float c2[16];
#pragma unroll
    for (int i = 0; i < 16; ++i) c2[i] = 0.f;
    __syncthreads();

    const size_t xpdir = (size_t)dir * MROWS * GATES;
    const int rowsel = (lane & 7) + ((lane >> 3) & 1) * 8;
    const int lkb = (lane & 16) ? 8 : 0;

    for (int s = 0; s < SEQ; ++s) {
        const int t = dir ? (SEQ - 1 - s) : s;
        const int rp = s & 1, wp = rp ^ 1;
        const int rOff16 = rp * 12288;          // bf16 elems per buffer
        const int wOff32 = wp * 6144;           // uint32 per buffer
        float acc[2][8][4];

        if (is_layer0) {
#pragma unroll
            for (int mt = 0; mt < 2; ++mt)
#pragma unroll
                for (int i = 0; i < 8; ++i) {
                    acc[mt][i][0] = biasv[i][0]; acc[mt][i][1] = biasv[i][1];
                    acc[mt][i][2] = biasv[i][0]; acc[mt][i][3] = biasv[i][1];
                }
            for (int q = 0; q < INP; ++q) {
                float2 w[8];
#pragma unroll
                for (int i = 0; i < 8; ++i)
                    w[i] = *reinterpret_cast<const float2*>(&w0sm[q * GATES + jcol[i]]);
#pragma unroll
                for (int mt = 0; mt < 2; ++mt)
#pragma unroll
                    for (int r8 = 0; r8 < 2; ++r8) {
                        float xv = xsm[rp][mt * 16 + r8 * 8 + (lane >> 2)][q];
#pragma unroll
                        for (int i = 0; i < 8; ++i) {
                            acc[mt][i][r8 * 2]     += xv * w[i].x;
                            acc[mt][i][r8 * 2 + 1] += xv * w[i].y;
                        }
                    }
            }
        } else {
#pragma unroll
            for (int mt = 0; mt < 2; ++mt)
#pragma unroll
                for (int r8 = 0; r8 < 2; ++r8) {
                    size_t m = (size_t)t * BATCH + b0 + mt * 16 + r8 * 8 + (lane >> 2);
                    const float* xr = xp + xpdir + m * GATES;
#pragma unroll
                    for (int i = 0; i < 8; ++i) {
                        float2 v = *reinterpret_cast<const float2*>(&xr[jcol[i]]);
                        acc[mt][i][r8 * 2] = v.x; acc[mt][i][r8 * 2 + 1] = v.y;
                    }
                }
        }

#pragma unroll 1
        for (int kc = 0; kc < 8; ++kc) {
            uint4 bf[8];
#pragma unroll
            for (int i = 0; i < 8; ++i)
                bf[i] = frag[(((kc * 8 + wn) * 8) + i) * 32 + lane];
#pragma unroll
            for (int mt = 0; mt < 2; ++mt) {
                uint32_t ah[4], al[4];
                ldmx4(ah, &hA[rOff16 + ((0 * 8 + kc) * 32 + mt * 16 + rowsel) * 24 + lkb]);
                ldmx4(al, &hA[rOff16 + ((1 * 8 + kc) * 32 + mt * 16 + rowsel) * 24 + lkb]);
#pragma unroll
                for (int i = 0; i < 8; ++i) mma16816(acc[mt][i], ah, bf[i].x, bf[i].y);
#pragma unroll
                for (int i = 0; i < 8; ++i) mma16816(acc[mt][i], ah, bf[i].z, bf[i].w);
#pragma unroll
                for (int i = 0; i < 8; ++i) mma16816(acc[mt][i], al, bf[i].x, bf[i].y);
            }
        }

        // epilogue: gates -> c,h ; h -> hA[wp] + (afrag | y)
#pragma unroll
        for (int mt = 0; mt < 2; ++mt) {
            uint32_t hi4[4], lo4[4];
#pragma unroll
            for (int r8 = 0; r8 < 2; ++r8)
#pragma unroll
                for (int blk = 0; blk < 2; ++blk) {
                    int c0i = r8 * 2;
                    float ii0 = acc[mt][blk][c0i],     ii1 = acc[mt][blk][c0i + 1];
                    float ff0 = acc[mt][2 + blk][c0i], ff1 = acc[mt][2 + blk][c0i + 1];
                    float gg0 = acc[mt][4 + blk][c0i], gg1 = acc[mt][4 + blk][c0i + 1];
                    float oo0 = acc[mt][6 + blk][c0i], oo1 = acc[mt][6 + blk][c0i + 1];
                    int ci = ((mt * 2 + r8) * 2 + blk) * 2;
                    float cc0 = c2[ci], cc1 = c2[ci + 1];
                    cc0 = sigf(ff0) * cc0 + sigf(ii0) * tanhf_(gg0);
                    cc1 = sigf(ff1) * cc1 + sigf(ii1) * tanhf_(gg1);
                    float h0 = sigf(oo0) * tanhf_(cc0);
                    float h1 = sigf(oo1) * tanhf_(cc1);
                    c2[ci] = cc0; c2[ci + 1] = cc1;
                    float h0h, h0l, h1h, h1l;
                    split_hl(h0, h0h, h0l); split_hl(h1, h1h, h1l);
                    int comp = blk * 2 + r8;
                    uint32_t phi = pack_bf2(h0h, h1h);
                    uint32_t plo = pack_bf2(h0l, h1l);
                    hi4[comp] = phi; lo4[comp] = plo;
                    int row = mt * 16 + r8 * 8 + (lane >> 2);
                    int base = row * 12 + blk * 4 + (lane & 3);
                    hA32[wOff32 + (wn * 32) * 12 + base]       = phi;
                    hA32[wOff32 + ((8 + wn) * 32) * 12 + base] = plo;
                    if (!af_out) {
                        int hc0 = wn * 16 + blk * 8 + (lane & 3) * 2;
                        *reinterpret_cast<float2*>(
                            &y[((size_t)(b0 + row) * SEQ + t) * 256 + dir * 128 + hc0]) =
                            make_float2(h0, h1);
                    }
                }
            if (af_out) {
                size_t mtg = (size_t)t * (BATCH / 16) + ((b0 + mt * 16) >> 4);
                int kcg = dir * 8 + wn;
                uint4* p = af_out + ((mtg * 16 + kcg) * 32 + lane) * 2;
                p[0] = make_uint4(hi4[0], hi4[1], hi4[2], hi4[3]);
                p[1] = make_uint4(lo4[0], lo4[1], lo4[2], lo4[3]);
            }
        }
        if (is_layer0 && s < SEQ - 1) {
            int tn = dir ? (SEQ - 2 - s) : (s + 1);
            for (int i = tid; i < BT * INP; i += 256) {
                int b = i / INP, q = i % INP;
                xsm[wp][b][q] = x[((size_t)(b0 + b) * SEQ + tn) * INP + q];
            }
        }
        __syncthreads();   // single barrier: hA[wp]/xsm[wp] visible; hA[rp] reads done
    }
}

__global__ void final_kernel(const float* __restrict__ y, const float* __restrict__ wout,
                             const float* __restrict__ bout, float* __restrict__ out)
{
    const int b = blockIdx.x;
    const int tid = threadIdx.x;
    const float* yr = y + (size_t)b * 15360;
    float s0 = 0.f, s1 = 0.f;
    for (int j = tid * 4; j < 15360; j += 128 * 4) {
        float4 v = *reinterpret_cast<const float4*>(&yr[j]);
        v.x = fmaxf(v.x, 0.f); v.y = fmaxf(v.y, 0.f);
        v.z = fmaxf(v.z, 0.f); v.w = fmaxf(v.w, 0.f);
        float4 w0 = __ldg(reinterpret_cast<const float4*>(&wout[j]));
        float4 w1 = __ldg(reinterpret_cast<const float4*>(&wout[15360 + j]));
        s0 += v.x * w0.x + v.y * w0.y + v.z * w0.z + v.w * w0.w;
        s1 += v.x * w1.x + v.y * w1.y + v.z * w1.z + v.w * w1.w;
    }
#pragma unroll
    for (int off = 16; off > 0; off >>= 1) {
        s0 += __shfl_down_sync(0xffffffffu, s0, off);
        s1 += __shfl_down_sync(0xffffffffu, s1, off);
    }
    __shared__ float r0[4], r1[4];
    int wid = tid >> 5;
    if ((tid & 31) == 0) { r0[wid] = s0; r1[wid] = s1; }
    __syncthreads();
    if (tid == 0) {
        out[(size_t)b * 2 + 0] = r0[0] + r0[1] + r0[2] + r0[3] + __ldg(&bout[0]);
        out[(size_t)b * 2 + 1] = r1[0] + r1[1] + r1[2] + r1[3] + __ldg(&bout[1]);
    }
}

extern "C" void kernel_launch(void* const* d_in, const int* in_sizes, int n_in,
                              void* d_out, int out_size) {
    const float* x = (const float*)d_in[0];
    WPtrs P;
    for (int i = 0; i < 6; i++) {
        P.w_ih[i] = (const float*)d_in[1 + 4 * i];
        P.w_hh[i] = (const float*)d_in[2 + 4 * i];
        P.b_ih[i] = (const float*)d_in[3 + 4 * i];
        P.b_hh[i] = (const float*)d_in[4 + 4 * i];
    }
    const float* w_out = (const float*)d_in[25];
    const float* b_out = (const float*)d_in[26];
    float* out = (float*)d_out;

    float *xp, *y0, *w0T; uint4 *bfrag, *wfrag, *afrag;
    cudaGetSymbolAddress((void**)&xp,    g_xp);
    cudaGetSymbolAddress((void**)&y0,    g_y0);
    cudaGetSymbolAddress((void**)&w0T,   g_w0T);
    cudaGetSymbolAddress((void**)&bfrag, g_bfrag);
    cudaGetSymbolAddress((void**)&wfrag, g_wfrag);
    cudaGetSymbolAddress((void**)&afrag, g_afrag);

    cudaFuncSetAttribute(lstm_rec_mma,
                         cudaFuncAttributeMaxDynamicSharedMemorySize, SMEM_REC);
    cudaFuncSetAttribute(gemm_smem,
                         cudaFuncAttributeMaxDynamicSharedMemorySize, SMEM_GEMM);

    prep_w0T<<<(2 * INP * GATES + 255) / 256, 256>>>(P, w0T);          // 0
    prep_bfrag<<<(BF_TOTAL + 255) / 256, 256>>>(P, bfrag);             // 1
    prep_wfrag<<<(WF_TOTAL + 255) / 256, 256>>>(P, wfrag);             // 2

    dim3 rgrid(BATCH / BT, 2);          // (128, 2)
    dim3 ggrid(GX, 4, 2);               // (16, 4, 2) = 128 CTAs x 512 thr

    lstm_rec_mma<<<rgrid, 256, SMEM_REC>>>(nullptr, x, w0T,            // 3
                                    P.b_ih[0], P.b_hh[0], P.b_ih[1], P.b_hh[1],
                                    wfrag + 0 * (size_t)WF_PER_W, wfrag + 1 * (size_t)WF_PER_W,
                                    y0, afrag, 1);
    dummy_kernel<<<1, 32>>>();                                         // 4
    gemm_smem<<<ggrid, 512, SMEM_GEMM>>>(afrag, bfrag,                 // 5
                              P.b_ih[2], P.b_hh[2], P.b_ih[3], P.b_hh[3], xp);
    lstm_rec_mma<<<rgrid, 256, SMEM_REC>>>(xp, nullptr, w0T,           // 6
                                    P.b_ih[2], P.b_hh[2], P.b_ih[3], P.b_hh[3],
                                    wfrag + 2 * (size_t)WF_PER_W, wfrag + 3 * (size_t)WF_PER_W,
                                    y0, afrag, 0);
    gemm_smem<<<ggrid, 512, SMEM_GEMM>>>(afrag, bfrag + BF_PER_LAYER,  // 7
                              P.b_ih[4], P.b_hh[4], P.b_ih[5], P.b_hh[5], xp);
    lstm_rec_mma<<<rgrid, 256, SMEM_REC>>>(xp, nullptr, w0T,           // 8
                                    P.b_ih[4], P.b_hh[4], P.b_ih[5], P.b_hh[5],
                                    wfrag + 4 * (size_t)WF_PER_W, wfrag + 5 * (size_t)WF_PER_W,
                                    y0, nullptr, 0);
    final_kernel<<<BATCH, 128>>>(y0, w_out, b_out, out);               // 9
}